// round 3
// baseline (speedup 1.0000x reference)
#include <cuda_runtime.h>
#include <cuda_bf16.h>
#include <math.h>

// Problem constants
#define BB   8
#define CIN  512
#define C1   256
#define DD   128
#define KK   32
#define NN   9216          // 96*96
#define SPLITK 16
#define KCHUNK (NN / SPLITK) // 576

// ---------------- scratch (device globals; no allocation) ----------------
__device__ float g_Theta[BB * C1 * NN];
__device__ float g_Phi  [BB * C1 * NN];
__device__ float g_G    [BB * C1 * NN];
__device__ float g_Fp   [SPLITK * BB * C1 * C1];  // split-K partials of f
__device__ float g_F    [BB * C1 * C1];           // softmaxed f
__device__ float g_Y    [BB * C1 * NN];
__device__ float g_Z    [BB * CIN * NN];
__device__ float g_ZD   [BB * DD * NN];
__device__ float g_Eacc [BB * KK * DD];
__device__ float g_Asum [BB * KK];
__device__ float g_Es   [BB * DD];
__device__ float g_gamma[BB * CIN];

// ---------------- zero the accumulated buffers ----------------
__global__ void zero_kernel() {
    int i = blockIdx.x * blockDim.x + threadIdx.x;
    if (i < BB * KK * DD) g_Eacc[i] = 0.f;
    if (i < BB * KK)      g_Asum[i] = 0.f;
    if (i < BB * DD)      g_Es[i]   = 0.f;
}

// ---------------- 128x128x8 register-tiled SGEMM (NN layout) ----------------
// C[b, m, n] = sum_k A[b?, m, k] * B[b, k, n] (+ bias[m]) (+ R[b, m, n])
template<bool RESID>
__global__ __launch_bounds__(256) void sgemm128(
    const float* __restrict__ Ag, long sA,
    const float* __restrict__ Bg, long sB,
    float* __restrict__ Cg, long sC,
    const float* __restrict__ bias,
    const float* __restrict__ Rg, long sR,
    int M, int N, int K)
{
    int b = blockIdx.z;
    const float* A = Ag + (long)b * sA;
    const float* Bm = Bg + (long)b * sB;
    float* C = Cg + (long)b * sC;
    const float* R = RESID ? (Rg + (long)b * sR) : nullptr;

    __shared__ float As[8][128];
    __shared__ float Bs[8][128];

    int tid = threadIdx.x;
    int m0 = blockIdx.y * 128, n0 = blockIdx.x * 128;
    int tx = tid & 15, ty = tid >> 4;

    float acc[8][8];
#pragma unroll
    for (int i = 0; i < 8; i++)
#pragma unroll
        for (int j = 0; j < 8; j++) acc[i][j] = 0.f;

    int arow = tid >> 1, akq = (tid & 1) * 4;   // A tile: 128 rows x 8 k
    int brow = tid >> 5, bnq = (tid & 31) * 4;  // B tile: 8 k x 128 n

    for (int k0 = 0; k0 < K; k0 += 8) {
        float4 av = *(const float4*)(A + (long)(m0 + arow) * K + k0 + akq);
        float4 bv = *(const float4*)(Bm + (long)(k0 + brow) * N + n0 + bnq);
        As[akq + 0][arow] = av.x;
        As[akq + 1][arow] = av.y;
        As[akq + 2][arow] = av.z;
        As[akq + 3][arow] = av.w;
        *(float4*)(&Bs[brow][bnq]) = bv;
        __syncthreads();
#pragma unroll
        for (int kk = 0; kk < 8; kk++) {
            float a[8], bb[8];
#pragma unroll
            for (int i = 0; i < 8; i++) a[i] = As[kk][(i >> 2) * 64 + ty * 4 + (i & 3)];
#pragma unroll
            for (int j = 0; j < 8; j++) bb[j] = Bs[kk][(j >> 2) * 64 + tx * 4 + (j & 3)];
#pragma unroll
            for (int i = 0; i < 8; i++)
#pragma unroll
                for (int j = 0; j < 8; j++) acc[i][j] += a[i] * bb[j];
        }
        __syncthreads();
    }

    // epilogue: two coalesced float4 stores per row-group
#pragma unroll
    for (int i = 0; i < 8; i++) {
        int m = m0 + (i >> 2) * 64 + ty * 4 + (i & 3);
        float bi = bias ? bias[m] : 0.f;
#pragma unroll
        for (int jj = 0; jj < 2; jj++) {
            int n = n0 + jj * 64 + tx * 4;
            float4 v;
            v.x = acc[i][jj * 4 + 0] + bi;
            v.y = acc[i][jj * 4 + 1] + bi;
            v.z = acc[i][jj * 4 + 2] + bi;
            v.w = acc[i][jj * 4 + 3] + bi;
            if (RESID) {
                float4 r = *(const float4*)(R + (long)m * N + n);
                v.x += r.x; v.y += r.y; v.z += r.z; v.w += r.w;
            }
            *(float4*)(C + (long)m * N + n) = v;
        }
    }
}

// ---------------- 64x64x16 NT GEMM with split-K partial outputs ----------------
// Fp[chunk, b, m, n] = sum_{k in chunk} A[b, m, k] * B[b, n, k]
__global__ __launch_bounds__(256) void sgemm_nt_split(
    const float* __restrict__ Ag, long sA,
    const float* __restrict__ Bg, long sB,
    float* __restrict__ Cp,
    int M, int N, int K)
{
    int bz = blockIdx.z;
    int b = bz / SPLITK, chunk = bz % SPLITK;
    const float* A = Ag + (long)b * sA;
    const float* Bm = Bg + (long)b * sB;
    float* C = Cp + ((long)chunk * BB + b) * ((long)M * N);

    __shared__ float As[16][64];
    __shared__ float Bs[16][64];

    int tid = threadIdx.x;
    int m0 = blockIdx.y * 64, n0 = blockIdx.x * 64;
    int tx = tid & 15, ty = tid >> 4;

    float acc[4][4];
#pragma unroll
    for (int i = 0; i < 4; i++)
#pragma unroll
        for (int j = 0; j < 4; j++) acc[i][j] = 0.f;

    int lrow = tid >> 2, lkq = (tid & 3) * 4;

    int kend = chunk * KCHUNK + KCHUNK;
    for (int k0 = chunk * KCHUNK; k0 < kend; k0 += 16) {
        float4 av = *(const float4*)(A + (long)(m0 + lrow) * K + k0 + lkq);
        float4 bv = *(const float4*)(Bm + (long)(n0 + lrow) * K + k0 + lkq);
        As[lkq + 0][lrow] = av.x; As[lkq + 1][lrow] = av.y;
        As[lkq + 2][lrow] = av.z; As[lkq + 3][lrow] = av.w;
        Bs[lkq + 0][lrow] = bv.x; Bs[lkq + 1][lrow] = bv.y;
        Bs[lkq + 2][lrow] = bv.z; Bs[lkq + 3][lrow] = bv.w;
        __syncthreads();
#pragma unroll
        for (int kk = 0; kk < 16; kk++) {
            float a[4], bb[4];
#pragma unroll
            for (int i = 0; i < 4; i++) a[i] = As[kk][ty * 4 + i];
#pragma unroll
            for (int j = 0; j < 4; j++) bb[j] = Bs[kk][tx * 4 + j];
#pragma unroll
            for (int i = 0; i < 4; i++)
#pragma unroll
                for (int j = 0; j < 4; j++) acc[i][j] += a[i] * bb[j];
        }
        __syncthreads();
    }
#pragma unroll
    for (int i = 0; i < 4; i++) {
        int m = m0 + ty * 4 + i;
        float4 v; v.x = acc[i][0]; v.y = acc[i][1]; v.z = acc[i][2]; v.w = acc[i][3];
        *(float4*)(C + (long)m * N + n0 + tx * 4) = v;
    }
}

// ---------------- row softmax over f (reduces split-K partials) ----------------
__global__ void softmax_rows(const float* __restrict__ Fp, float* __restrict__ F)
{
    int row = blockIdx.x;           // 0..BB*C1-1
    int t = threadIdx.x;            // 256
    int b = row >> 8, c = row & 255;
    long base = (long)b * C1 * C1 + (long)c * C1 + t;
    float v = 0.f;
#pragma unroll
    for (int ch = 0; ch < SPLITK; ch++)
        v += Fp[(long)ch * BB * C1 * C1 + base];

    __shared__ float sh[256];
    sh[t] = v; __syncthreads();
    for (int o = 128; o; o >>= 1) { if (t < o) sh[t] = fmaxf(sh[t], sh[t + o]); __syncthreads(); }
    float m = sh[0]; __syncthreads();
    float e = expf(v - m);
    sh[t] = e; __syncthreads();
    for (int o = 128; o; o >>= 1) { if (t < o) sh[t] += sh[t + o]; __syncthreads(); }
    float inv = 1.f / sh[0];
    F[base] = e * inv;
}

// ---------------- fused dist -> softmax(A) -> E accumulation ----------------
__global__ __launch_bounds__(256) void encode_kernel(
    const float* __restrict__ ZD,          // (B, D, N)
    const float* __restrict__ codewords,   // (K, D)
    const float* __restrict__ scale,       // (K)
    float* __restrict__ Eacc,              // (B, K, D)
    float* __restrict__ Asum)              // (B, K)
{
    int b = blockIdx.y;
    __shared__ float cs[KK][DD + 1];
    __shared__ float cn[KK];
    __shared__ float sc[KK];
    __shared__ float xs[DD][33];   // 128 x 32 tile of x, padded
    __shared__ float Ash[8][KK];

    int tid = threadIdx.x;
    int lane = tid & 31, wid = tid >> 5;

    for (int i = tid; i < KK * DD; i += 256) cs[i >> 7][i & 127] = codewords[i];
    if (tid < KK) sc[tid] = scale[tid];
    __syncthreads();
    if (tid < KK) {
        float s = 0.f;
        for (int d = 0; d < DD; d++) { float c = cs[tid][d]; s += c * c; }
        cn[tid] = s;
    }
    __syncthreads();

    float ereg[16];
#pragma unroll
    for (int i = 0; i < 16; i++) ereg[i] = 0.f;
    float asum_local = 0.f;
    int myk = tid >> 3, myd0 = tid & 7;

    for (int t = blockIdx.x; t < NN / 32; t += gridDim.x) {
        int n0 = t * 32;
        // load 128 x 32 x-tile (coalesced), store transposed-friendly
#pragma unroll
        for (int r = 0; r < 4; r++) {
            int d = (tid >> 3) + r * 32;
            int nq = (tid & 7) * 4;
            float4 v = *(const float4*)(ZD + ((long)b * DD + d) * NN + n0 + nq);
            xs[d][nq + 0] = v.x; xs[d][nq + 1] = v.y;
            xs[d][nq + 2] = v.z; xs[d][nq + 3] = v.w;
        }
        __syncthreads();

        for (int round = 0; round < 4; round++) {
            int n = round * 8 + wid;  // each warp owns one n
            float xx = 0.f;
            for (int d = lane; d < DD; d += 32) { float x = xs[d][n]; xx += x * x; }
            for (int o = 16; o; o >>= 1) xx += __shfl_xor_sync(0xffffffffu, xx, o);
            float dot = 0.f;
#pragma unroll 8
            for (int d = 0; d < DD; d++) dot += xs[d][n] * cs[lane][d];
            float s = sc[lane] * (xx - 2.f * dot + cn[lane]);
            float m = s;
            for (int o = 16; o; o >>= 1) m = fmaxf(m, __shfl_xor_sync(0xffffffffu, m, o));
            float e = __expf(s - m);
            float ssum = e;
            for (int o = 16; o; o >>= 1) ssum += __shfl_xor_sync(0xffffffffu, ssum, o);
            float a = e / ssum;
            Ash[wid][lane] = a;
            asum_local += a;
            __syncthreads();
#pragma unroll
            for (int nn = 0; nn < 8; nn++) {
                float av = Ash[nn][myk];
                int ncol = round * 8 + nn;
#pragma unroll
                for (int i = 0; i < 16; i++)
                    ereg[i] += av * xs[myd0 + 8 * i][ncol];
            }
            __syncthreads();
        }
    }
#pragma unroll
    for (int i = 0; i < 16; i++)
        atomicAdd(&Eacc[((long)b * KK + myk) * DD + myd0 + 8 * i], ereg[i]);
    atomicAdd(&Asum[b * KK + lane], asum_local);
}

// ---------------- BN over K channels + Es = sum_k relu(norm(E)) ----------------
__global__ void bn_es_kernel(const float* __restrict__ Eacc,
                             const float* __restrict__ Asum,
                             const float* __restrict__ codewords,
                             float* __restrict__ Es)
{
    int k = blockIdx.x;       // 0..31
    int tid = threadIdx.x;    // 256
    __shared__ double shs[256], shs2[256];
    float vals[4];
    double s = 0.0, s2 = 0.0;
#pragma unroll
    for (int i = 0; i < 4; i++) {
        int idx = tid + i * 256;            // (b,d) flat over 1024
        int b = idx >> 7, d = idx & 127;
        float v = Eacc[((long)b * KK + k) * DD + d] - Asum[b * KK + k] * codewords[k * DD + d];
        vals[i] = v; s += v; s2 += (double)v * v;
    }
    shs[tid] = s; shs2[tid] = s2; __syncthreads();
    for (int o = 128; o; o >>= 1) {
        if (tid < o) { shs[tid] += shs[tid + o]; shs2[tid] += shs2[tid + o]; }
        __syncthreads();
    }
    double mean = shs[0] / 1024.0;
    double var = shs2[0] / 1024.0 - mean * mean;
    float inv = rsqrtf((float)var + 1e-5f);
    float mf = (float)mean;
#pragma unroll
    for (int i = 0; i < 4; i++) {
        int idx = tid + i * 256;
        int b = idx >> 7, d = idx & 127;
        float e = (vals[i] - mf) * inv;
        if (e > 0.f) atomicAdd(&Es[b * DD + d], e);
    }
}

// ---------------- gamma = sigmoid(Es @ W_fc^T + b_fc) ----------------
__global__ void gamma_kernel(const float* __restrict__ Es,
                             const float* __restrict__ W_fc,
                             const float* __restrict__ b_fc,
                             float* __restrict__ gamma)
{
    int idx = blockIdx.x * blockDim.x + threadIdx.x;  // 0..BB*CIN-1
    int b = idx / CIN, c = idx % CIN;
    float s = b_fc[c];
    for (int d = 0; d < DD; d++) s += Es[b * DD + d] * W_fc[c * DD + d];
    gamma[idx] = 1.f / (1.f + expf(-s));
}

// ---------------- out = Z * gamma broadcast ----------------
__global__ void scale_out_kernel(const float* __restrict__ Z,
                                 const float* __restrict__ gamma,
                                 float* __restrict__ out)
{
    long idx = (long)blockIdx.x * blockDim.x + threadIdx.x;  // float4 index
    const long total4 = (long)BB * CIN * NN / 4;
    if (idx >= total4) return;
    float4 z = ((const float4*)Z)[idx];
    float gm = gamma[(idx * 4) / NN];
    z.x *= gm; z.y *= gm; z.z *= gm; z.w *= gm;
    ((float4*)out)[idx] = z;
}

// ---------------- launch ----------------
extern "C" void kernel_launch(void* const* d_in, const int* in_sizes, int n_in,
                              void* d_out, int out_size)
{
    const float* X        = (const float*)d_in[0];
    const float* W_theta  = (const float*)d_in[1];
    const float* b_theta  = (const float*)d_in[2];
    const float* W_phi    = (const float*)d_in[3];
    const float* b_phi    = (const float*)d_in[4];
    const float* W_g      = (const float*)d_in[5];
    const float* b_g      = (const float*)d_in[6];
    const float* W2       = (const float*)d_in[7];
    const float* b2       = (const float*)d_in[8];
    const float* W3       = (const float*)d_in[9];
    const float* b3       = (const float*)d_in[10];
    const float* codewords= (const float*)d_in[11];
    const float* scale    = (const float*)d_in[12];
    const float* W_fc     = (const float*)d_in[13];
    const float* b_fc     = (const float*)d_in[14];

    float *Theta, *Phi, *G, *Fp, *F, *Y, *Z, *ZD, *Eacc, *Asum, *Es, *gammaB;
    cudaGetSymbolAddress((void**)&Theta, g_Theta);
    cudaGetSymbolAddress((void**)&Phi,   g_Phi);
    cudaGetSymbolAddress((void**)&G,     g_G);
    cudaGetSymbolAddress((void**)&Fp,    g_Fp);
    cudaGetSymbolAddress((void**)&F,     g_F);
    cudaGetSymbolAddress((void**)&Y,     g_Y);
    cudaGetSymbolAddress((void**)&Z,     g_Z);
    cudaGetSymbolAddress((void**)&ZD,    g_ZD);
    cudaGetSymbolAddress((void**)&Eacc,  g_Eacc);
    cudaGetSymbolAddress((void**)&Asum,  g_Asum);
    cudaGetSymbolAddress((void**)&Es,    g_Es);
    cudaGetSymbolAddress((void**)&gammaB,g_gamma);

    const long sX  = (long)CIN * NN;   // X batch stride
    const long sC1 = (long)C1 * NN;    // (B, 256, N) stride
    const long sZD = (long)DD * NN;

    zero_kernel<<<128, 256>>>();

    // theta / phi / g : (256 x 512) @ (512 x 9216) per batch
    dim3 gQ(NN / 128, C1 / 128, BB);
    sgemm128<false><<<gQ, 256>>>(W_theta, 0, X, sX, Theta, sC1, b_theta, nullptr, 0, C1, NN, CIN);
    sgemm128<false><<<gQ, 256>>>(W_phi,   0, X, sX, Phi,   sC1, b_phi,   nullptr, 0, C1, NN, CIN);
    sgemm128<false><<<gQ, 256>>>(W_g,     0, X, sX, G,     sC1, b_g,     nullptr, 0, C1, NN, CIN);

    // f = theta @ phi^T, split-K
    dim3 gF(C1 / 64, C1 / 64, BB * SPLITK);
    sgemm_nt_split<<<gF, 256>>>(Theta, sC1, Phi, sC1, Fp, C1, C1, NN);
    softmax_rows<<<BB * C1, 256>>>(Fp, F);

    // y = f @ g
    dim3 gY(NN / 128, C1 / 128, BB);
    sgemm128<false><<<gY, 256>>>(F, (long)C1 * C1, G, sC1, Y, sC1, nullptr, nullptr, 0, C1, NN, C1);

    // z = W2 @ y + b2 + X
    dim3 gZ(NN / 128, CIN / 128, BB);
    sgemm128<true><<<gZ, 256>>>(W2, 0, Y, sC1, Z, sX, b2, X, sX, CIN, NN, C1);

    // z_ = W3 @ z + b3
    dim3 gD(NN / 128, DD / 128, BB);
    sgemm128<false><<<gD, 256>>>(W3, 0, Z, sX, ZD, sZD, b3, nullptr, 0, DD, NN, CIN);

    // encoding: dist -> softmax -> E partial sums
    encode_kernel<<<dim3(96, BB), 256>>>(ZD, codewords, scale, Eacc, Asum);

    // batch norm over K + Es
    bn_es_kernel<<<KK, 256>>>(Eacc, Asum, codewords, Es);

    // gamma
    gamma_kernel<<<(BB * CIN) / 256, 256>>>(Es, W_fc, b_fc, gammaB);

    // out = z * gamma
    long total4 = (long)BB * CIN * NN / 4;
    scale_out_kernel<<<(unsigned)((total4 + 255) / 256), 256>>>(Z, gammaB, (float*)d_out);
}

// round 6
// speedup vs baseline: 1.0336x; 1.0336x over previous
#include <cuda_runtime.h>
#include <cuda_bf16.h>
#include <math.h>
#include <stdint.h>

#define BB 8
#define CIN 512
#define C1 256
#define DD 128
#define KK 32
#define NN 9216
#define ROWS (BB*NN)
#define FS 9
typedef __nv_bfloat16 bf16;
typedef unsigned int u32;

// ------------- scratch (device globals) -------------
__device__ bf16 g_Xh[ROWS*CIN], g_Xm[ROWS*CIN], g_Xl[ROWS*CIN];
__device__ bf16 g_Wth[C1*CIN], g_Wtm[C1*CIN], g_Wtl[C1*CIN];
__device__ bf16 g_Wph[C1*CIN], g_Wpm[C1*CIN], g_Wpl[C1*CIN];
__device__ bf16 g_Wgh[C1*CIN], g_Wgm[C1*CIN];
__device__ bf16 g_W2h[CIN*C1], g_W2m[CIN*C1];
__device__ bf16 g_W3h[DD*CIN], g_W3m[DD*CIN];
__device__ float g_Tt[ROWS*C1], g_Pt[ROWS*C1];
__device__ bf16 g_Th[ROWS*C1], g_Tm[ROWS*C1], g_Tl[ROWS*C1];
__device__ bf16 g_Phh[ROWS*C1], g_Pmm[ROWS*C1], g_Pll[ROWS*C1];
__device__ bf16 g_Gh[ROWS*C1], g_Gm[ROWS*C1];
__device__ float g_Fp[FS*BB*C1*C1];
__device__ bf16 g_Fh[BB*C1*C1], g_Fm[BB*C1*C1];
__device__ bf16 g_Yh[ROWS*C1], g_Ym[ROWS*C1];
__device__ float g_Zt[ROWS*CIN];
__device__ bf16 g_Zh[ROWS*CIN], g_Zm[ROWS*CIN];
__device__ float g_ZDt[ROWS*DD];
__device__ float g_Eacc[BB*KK*DD], g_Asum[BB*KK], g_Es[BB*DD], g_gam[BB*CIN];

// ------------- helpers -------------
__device__ __forceinline__ u32 smem_u32(const void* p) {
    u32 a;
    asm("{ .reg .u64 t; cvta.to.shared.u64 t, %1; cvt.u32.u64 %0, t; }" : "=r"(a) : "l"(p));
    return a;
}
__device__ __forceinline__ void ldm_x4(u32* r, u32 addr) {
    asm volatile("ldmatrix.sync.aligned.m8n8.x4.shared.b16 {%0,%1,%2,%3}, [%4];"
        : "=r"(r[0]), "=r"(r[1]), "=r"(r[2]), "=r"(r[3]) : "r"(addr));
}
__device__ __forceinline__ void mma16816(float* d, const u32* a, const u32* b) {
    asm volatile(
        "mma.sync.aligned.m16n8k16.row.col.f32.bf16.bf16.f32 "
        "{%0,%1,%2,%3}, {%4,%5,%6,%7}, {%8,%9}, {%0,%1,%2,%3};"
        : "+f"(d[0]), "+f"(d[1]), "+f"(d[2]), "+f"(d[3])
        : "r"(a[0]), "r"(a[1]), "r"(a[2]), "r"(a[3]), "r"(b[0]), "r"(b[1]));
}
__device__ __forceinline__ float2 rd2bf(const bf16* p, long i) {
    u32 v = *(const u32*)(p + i);
    __nv_bfloat162 b = *(__nv_bfloat162*)&v;
    return make_float2(__bfloat162float(b.x), __bfloat162float(b.y));
}
__device__ __forceinline__ void st2bf(bf16* p, long i, float a, float b_) {
    __nv_bfloat162 v(__float2bfloat16(a), __float2bfloat16(b_));
    *(u32*)(p + i) = *(u32*)&v;
}

// ============ mma.sync bf16-split GEMM ============
// C[z; m, n] = sum over products of A_part[b; m, k] * B_part[b; n, k], K-major.
// CTA tile 128x128, BK=32, 8 warps (2m x 4n), warp tile 64x32.
template<int NPROD>
__global__ __launch_bounds__(256, 1) void mma_gemm(
    const bf16* __restrict__ Ah, const bf16* __restrict__ Am, const bf16* __restrict__ Al,
    int lda, long sAb,
    const bf16* __restrict__ Bh, const bf16* __restrict__ Bm, const bf16* __restrict__ Bl,
    int ldb, long sBb,
    float* __restrict__ C, bf16* __restrict__ Ch, bf16* __restrict__ Cm,
    int ldc, long sCz,
    const float* __restrict__ bias,
    const bf16* __restrict__ Rh, const bf16* __restrict__ Rm, const bf16* __restrict__ Rl,
    int KS, int S, int KCL)  // KCL = log2(KS/32)
{
    __shared__ __align__(16) char sA[2][128 * 80];
    __shared__ __align__(16) char sB[2][128 * 80];

    const int tid = threadIdx.x, lane = tid & 31, wid = tid >> 5;
    const int wm = wid & 1, wn = wid >> 1;
    const int z = blockIdx.z, b = z / S, s = z % S;
    const long m0 = (long)blockIdx.y * 128;
    const int n0 = blockIdx.x * 128;

    const long abase = (long)b * sAb + m0 * lda + (long)s * KS;
    const long bbase = (long)b * sBb + (long)n0 * ldb + (long)s * KS;

    const int lrow = tid >> 2, lq = tid & 3;
    const int NCH = NPROD << KCL;
    const int kmask = (1 << KCL) - 1;

    float acc[4][4][4];
#pragma unroll
    for (int i = 0; i < 4; i++)
#pragma unroll
        for (int j = 0; j < 4; j++)
#pragma unroll
            for (int r = 0; r < 4; r++) acc[i][j][r] = 0.f;

    float4 pa0, pa1, pb0, pb1;
    auto fetch = [&](int c) {
        int p = c >> KCL, k0 = (c & kmask) << 5;
        int pa_, pb_;
        if (NPROD == 6) {
            pa_ = (p == 2 || p == 3) ? 1 : (p == 5 ? 2 : 0);
            pb_ = (p == 1 || p == 3) ? 1 : (p == 4 ? 2 : 0);
        } else {
            pa_ = (p == 2) ? 1 : 0;
            pb_ = (p == 1) ? 1 : 0;
        }
        const bf16* ag = (pa_ == 0 ? Ah : (pa_ == 1 ? Am : Al)) + abase + k0;
        const bf16* bg = (pb_ == 0 ? Bh : (pb_ == 1 ? Bm : Bl)) + bbase + k0;
        pa0 = *(const float4*)(ag + (long)lrow * lda + lq * 8);
        pa1 = *(const float4*)(ag + (long)(lrow + 64) * lda + lq * 8);
        pb0 = *(const float4*)(bg + (long)lrow * ldb + lq * 8);
        pb1 = *(const float4*)(bg + (long)(lrow + 64) * ldb + lq * 8);
    };
    auto store_st = [&](int st) {
        *(float4*)&sA[st][lrow * 80 + lq * 16] = pa0;
        *(float4*)&sA[st][(lrow + 64) * 80 + lq * 16] = pa1;
        *(float4*)&sB[st][lrow * 80 + lq * 16] = pb0;
        *(float4*)&sB[st][(lrow + 64) * 80 + lq * 16] = pb1;
    };

    // precompute ldmatrix lane offsets
    u32 aoff[4], boff[2];
#pragma unroll
    for (int t = 0; t < 4; t++)
        aoff[t] = (u32)((wm * 64 + t * 16 + (lane & 15)) * 80 + (lane >> 4) * 16);
#pragma unroll
    for (int u = 0; u < 2; u++)
        boff[u] = (u32)((wn * 32 + u * 16 + (lane & 7) + (lane >> 4) * 8) * 80
                        + ((lane >> 3) & 1) * 16);
    const u32 sAb0 = smem_u32(sA[0]), sAb1 = smem_u32(sA[1]);
    const u32 sBb0 = smem_u32(sB[0]), sBb1 = smem_u32(sB[1]);

    fetch(0);
    store_st(0);
    __syncthreads();

    for (int c = 0; c < NCH; c++) {
        int st = c & 1;
        if (c + 1 < NCH) fetch(c + 1);
        u32 sa = st ? sAb1 : sAb0;
        u32 sb = st ? sBb1 : sBb0;
#pragma unroll
        for (int kk = 0; kk < 2; kk++) {
            u32 af[4][4], bfr[2][4];
#pragma unroll
            for (int t = 0; t < 4; t++) ldm_x4(af[t], sa + aoff[t] + kk * 32);
#pragma unroll
            for (int u = 0; u < 2; u++) ldm_x4(bfr[u], sb + boff[u] + kk * 32);
#pragma unroll
            for (int mi = 0; mi < 4; mi++)
#pragma unroll
                for (int ni = 0; ni < 4; ni++)
                    mma16816(acc[mi][ni], af[mi], &bfr[ni >> 1][(ni & 1) * 2]);
        }
        __syncthreads();
        if (c + 1 < NCH) {
            store_st(st ^ 1);
            __syncthreads();
        }
    }

    // ---- epilogue ----
    const int mrow = lane >> 2, nc2 = (lane & 3) * 2;
#pragma unroll
    for (int mi = 0; mi < 4; mi++) {
#pragma unroll
        for (int rp = 0; rp < 2; rp++) {
            long row = m0 + wm * 64 + mi * 16 + mrow + rp * 8;
            long rowoff = (long)z * sCz + row * ldc;
#pragma unroll
            for (int ni = 0; ni < 4; ni++) {
                int col = n0 + wn * 32 + ni * 8 + nc2;
                float v0 = acc[mi][ni][rp * 2 + 0];
                float v1 = acc[mi][ni][rp * 2 + 1];
                if (bias) { v0 += bias[col]; v1 += bias[col + 1]; }
                if (Rh) {
                    float2 h = rd2bf(Rh, rowoff + col);
                    float2 m = rd2bf(Rm, rowoff + col);
                    float2 l = rd2bf(Rl, rowoff + col);
                    v0 += h.x + m.x + l.x;
                    v1 += h.y + m.y + l.y;
                }
                if (C) *(float2*)&C[rowoff + col] = make_float2(v0, v1);
                if (Ch) {
                    float h0 = __bfloat162float(__float2bfloat16(v0));
                    float h1 = __bfloat162float(__float2bfloat16(v1));
                    st2bf(Ch, rowoff + col, v0, v1);
                    st2bf(Cm, rowoff + col, v0 - h0, v1 - h1);
                }
            }
        }
    }
}

// ------------- tiled transpose + 3-way bf16 split -------------
// src (batch, R, C) fp32 -> dst (batch, C, R) bf16 h/m/l
__global__ void tsplit(const float* __restrict__ src, bf16* __restrict__ h,
                       bf16* __restrict__ m, bf16* __restrict__ l, int R, int C)
{
    __shared__ float ts[32][33];
    int b = blockIdx.z;
    long o = (long)b * R * C;
    int c0 = blockIdx.x * 32, r0 = blockIdx.y * 32;
    int tx = threadIdx.x, ty = threadIdx.y;
#pragma unroll
    for (int i = 0; i < 4; i++)
        ts[ty + i * 8][tx] = src[o + (long)(r0 + ty + i * 8) * C + c0 + tx];
    __syncthreads();
#pragma unroll
    for (int i = 0; i < 4; i++) {
        int c = c0 + ty + i * 8;
        float v = ts[tx][ty + i * 8];
        long idx = o + (long)c * R + r0 + tx;
        bf16 hh = __float2bfloat16(v);
        float r1 = v - __bfloat162float(hh);
        bf16 mm = __float2bfloat16(r1);
        h[idx] = hh; m[idx] = mm;
        if (l) l[idx] = __float2bfloat16(r1 - __bfloat162float(mm));
    }
}

// ------------- elementwise weight split -------------
__global__ void split_w(const float* __restrict__ s, bf16* __restrict__ h,
                        bf16* __restrict__ m, bf16* __restrict__ l, int n)
{
    int i = blockIdx.x * 256 + threadIdx.x;
    if (i >= n) return;
    float v = s[i];
    bf16 hh = __float2bfloat16(v);
    float r1 = v - __bfloat162float(hh);
    bf16 mm = __float2bfloat16(r1);
    h[i] = hh; m[i] = mm;
    if (l) l[i] = __float2bfloat16(r1 - __bfloat162float(mm));
}

// ------------- softmax over f (reduce FS partials), emit bf16 h/m -------------
__global__ void softmax9(const float* __restrict__ Fp, bf16* __restrict__ Fh, bf16* __restrict__ Fm)
{
    int row = blockIdx.x, t = threadIdx.x;
    int b = row >> 8, c = row & 255;
    long base = (long)(b * FS) * 65536 + c * 256 + t;
    float v = 0.f;
#pragma unroll
    for (int s2 = 0; s2 < FS; s2++) v += Fp[base + (long)s2 * 65536];
    __shared__ float sh[256];
    sh[t] = v; __syncthreads();
    for (int o = 128; o; o >>= 1) { if (t < o) sh[t] = fmaxf(sh[t], sh[t + o]); __syncthreads(); }
    float mx = sh[0]; __syncthreads();
    float e = expf(v - mx);
    sh[t] = e; __syncthreads();
    for (int o = 128; o; o >>= 1) { if (t < o) sh[t] += sh[t + o]; __syncthreads(); }
    float r = e / sh[0];
    long o2 = (long)b * 65536 + c * 256 + t;
    bf16 h = __float2bfloat16(r);
    Fh[o2] = h;
    Fm[o2] = __float2bfloat16(r - __bfloat162float(h));
}

// ------------- zero accumulators -------------
__global__ void zero_kernel() {
    int i = blockIdx.x * blockDim.x + threadIdx.x;
    if (i < BB * KK * DD) g_Eacc[i] = 0.f;
    if (i < BB * KK)      g_Asum[i] = 0.f;
    if (i < BB * DD)      g_Es[i]   = 0.f;
}

// ------------- fused dist -> softmax(A) -> E accumulation -------------
__global__ __launch_bounds__(256) void encode_kernel(
    const float* __restrict__ ZDt,        // (B*N, 128)
    const float* __restrict__ codewords, const float* __restrict__ scale,
    float* __restrict__ Eacc, float* __restrict__ Asum)
{
    int b = blockIdx.y;
    __shared__ float cs[KK][DD + 1];
    __shared__ float cn[KK], sc[KK];
    __shared__ float xs[DD][33];
    __shared__ float Ash[8][KK];
    int tid = threadIdx.x, lane = tid & 31, wid = tid >> 5;

    for (int i = tid; i < KK * DD; i += 256) cs[i >> 7][i & 127] = codewords[i];
    if (tid < KK) sc[tid] = scale[tid];
    __syncthreads();
    if (tid < KK) {
        float s = 0.f;
        for (int d = 0; d < DD; d++) { float c = cs[tid][d]; s += c * c; }
        cn[tid] = s;
    }
    __syncthreads();

    float ereg[16];
#pragma unroll
    for (int i = 0; i < 16; i++) ereg[i] = 0.f;
    float asum_local = 0.f;
    int myk = tid >> 3, myd0 = tid & 7;

    for (int t = blockIdx.x; t < NN / 32; t += gridDim.x) {
        int n0 = t * 32;
#pragma unroll
        for (int r = 0; r < 4; r++) {
            int idx = r * 256 + tid;
            int n = idx >> 5, d4 = (idx & 31) * 4;
            float4 v = *(const float4*)(ZDt + ((long)b * NN + n0 + n) * DD + d4);
            xs[d4][n] = v.x; xs[d4 + 1][n] = v.y; xs[d4 + 2][n] = v.z; xs[d4 + 3][n] = v.w;
        }
        __syncthreads();
        for (int round = 0; round < 4; round++) {
            int n = round * 8 + wid;
            float xx = 0.f;
            for (int d = lane; d < DD; d += 32) { float x = xs[d][n]; xx += x * x; }
            for (int o = 16; o; o >>= 1) xx += __shfl_xor_sync(0xffffffffu, xx, o);
            float dot = 0.f;
#pragma unroll 8
            for (int d = 0; d < DD; d++) dot += xs[d][n] * cs[lane][d];
            float s = sc[lane] * (xx - 2.f * dot + cn[lane]);
            float mx = s;
            for (int o = 16; o; o >>= 1) mx = fmaxf(mx, __shfl_xor_sync(0xffffffffu, mx, o));
            float e = __expf(s - mx);
            float ssum = e;
            for (int o = 16; o; o >>= 1) ssum += __shfl_xor_sync(0xffffffffu, ssum, o);
            float a = e / ssum;
            Ash[wid][lane] = a;
            asum_local += a;
            __syncthreads();
#pragma unroll
            for (int nn2 = 0; nn2 < 8; nn2++) {
                float av = Ash[nn2][myk];
                int ncol = round * 8 + nn2;
#pragma unroll
                for (int i = 0; i < 16; i++)
                    ereg[i] += av * xs[myd0 + 8 * i][ncol];
            }
            __syncthreads();
        }
    }
#pragma unroll
    for (int i = 0; i < 16; i++)
        atomicAdd(&Eacc[((long)b * KK + myk) * DD + myd0 + 8 * i], ereg[i]);
    atomicAdd(&Asum[b * KK + lane], asum_local);
}

// ------------- BN over K + Es -------------
__global__ void bn_es_kernel(const float* __restrict__ Eacc, const float* __restrict__ Asum,
                             const float* __restrict__ codewords, float* __restrict__ Es)
{
    int k = blockIdx.x, tid = threadIdx.x;
    __shared__ double shs[256], shs2[256];
    float vals[4];
    double s = 0.0, s2 = 0.0;
#pragma unroll
    for (int i = 0; i < 4; i++) {
        int idx = tid + i * 256;
        int b = idx >> 7, d = idx & 127;
        float v = Eacc[((long)b * KK + k) * DD + d] - Asum[b * KK + k] * codewords[k * DD + d];
        vals[i] = v; s += v; s2 += (double)v * v;
    }
    shs[tid] = s; shs2[tid] = s2; __syncthreads();
    for (int o = 128; o; o >>= 1) {
        if (tid < o) { shs[tid] += shs[tid + o]; shs2[tid] += shs2[tid + o]; }
        __syncthreads();
    }
    double mean = shs[0] / 1024.0;
    double var = shs2[0] / 1024.0 - mean * mean;
    float inv = rsqrtf((float)var + 1e-5f);
    float mf = (float)mean;
#pragma unroll
    for (int i = 0; i < 4; i++) {
        int idx = tid + i * 256;
        int b = idx >> 7, d = idx & 127;
        float e = (vals[i] - mf) * inv;
        if (e > 0.f) atomicAdd(&Es[b * DD + d], e);
    }
}

// ------------- gamma = sigmoid(Es @ W_fc^T + b_fc) -------------
__global__ void gamma_kernel(const float* __restrict__ Es, const float* __restrict__ W_fc,
                             const float* __restrict__ b_fc, float* __restrict__ gam)
{
    int idx = blockIdx.x * blockDim.x + threadIdx.x;
    int b = idx / CIN, c = idx % CIN;
    float s = b_fc[c];
    for (int d = 0; d < DD; d++) s += Es[b * DD + d] * W_fc[c * DD + d];
    gam[idx] = 1.f / (1.f + expf(-s));
}

// ------------- transpose back + gamma scale -> output (B, C, N) -------------
__global__ void tscale_out(const float* __restrict__ Zt, const float* __restrict__ gam,
                           float* __restrict__ out)
{
    __shared__ float ts[32][33];
    int b = blockIdx.z;
    int n0 = blockIdx.x * 32, c0 = blockIdx.y * 32;
    int tx = threadIdx.x, ty = threadIdx.y;
#pragma unroll
    for (int i = 0; i < 4; i++)
        ts[ty + i * 8][tx] = Zt[((long)b * NN + n0 + ty + i * 8) * CIN + c0 + tx];
    __syncthreads();
#pragma unroll
    for (int i = 0; i < 4; i++) {
        int c = c0 + ty + i * 8;
        out[((long)b * CIN + c) * NN + n0 + tx] = ts[tx][ty + i * 8] * gam[b * CIN + c];
    }
}

// ------------- launch -------------
#define GA(T, p, s) T* p; cudaGetSymbolAddress((void**)&p, s)

extern "C" void kernel_launch(void* const* d_in, const int* in_sizes, int n_in,
                              void* d_out, int out_size)
{
    const float* X        = (const float*)d_in[0];
    const float* W_theta  = (const float*)d_in[1];
    const float* b_theta  = (const float*)d_in[2];
    const float* W_phi    = (const float*)d_in[3];
    const float* b_phi    = (const float*)d_in[4];
    const float* W_g      = (const float*)d_in[5];
    const float* b_g      = (const float*)d_in[6];
    const float* W2       = (const float*)d_in[7];
    const float* b2       = (const float*)d_in[8];
    const float* W3       = (const float*)d_in[9];
    const float* b3       = (const float*)d_in[10];
    const float* codewords= (const float*)d_in[11];
    const float* scale    = (const float*)d_in[12];
    const float* W_fc     = (const float*)d_in[13];
    const float* b_fc     = (const float*)d_in[14];

    GA(bf16, Xh, g_Xh); GA(bf16, Xm, g_Xm); GA(bf16, Xl, g_Xl);
    GA(bf16, Wth, g_Wth); GA(bf16, Wtm, g_Wtm); GA(bf16, Wtl, g_Wtl);
    GA(bf16, Wph, g_Wph); GA(bf16, Wpm, g_Wpm); GA(bf16, Wpl, g_Wpl);
    GA(bf16, Wgh, g_Wgh); GA(bf16, Wgm, g_Wgm);
    GA(bf16, W2h, g_W2h); GA(bf16, W2m, g_W2m);
    GA(bf16, W3h, g_W3h); GA(bf16, W3m, g_W3m);
    GA(float, Tt, g_Tt); GA(float, Pt, g_Pt);
    GA(bf16, Th, g_Th); GA(bf16, Tm, g_Tm); GA(bf16, Tl, g_Tl);
    GA(bf16, Ph, g_Phh); GA(bf16, Pm, g_Pmm); GA(bf16, Pl, g_Pll);
    GA(bf16, Gh, g_Gh); GA(bf16, Gm, g_Gm);
    GA(float, Fp, g_Fp);
    GA(bf16, Fh, g_Fh); GA(bf16, Fm, g_Fm);
    GA(bf16, Yh, g_Yh); GA(bf16, Ym, g_Ym);
    GA(float, Zt, g_Zt);
    GA(bf16, Zh, g_Zh); GA(bf16, Zm, g_Zm);
    GA(float, ZDt, g_ZDt);
    GA(float, Eacc, g_Eacc); GA(float, Asum, g_Asum);
    GA(float, Es, g_Es); GA(float, gamB, g_gam);

    zero_kernel<<<128, 256>>>();
    // X (B,512,9216) -> Xt (B*N, 512) split h/m/l
    tsplit<<<dim3(288, 16, BB), dim3(32, 8)>>>(X, Xh, Xm, Xl, CIN, NN);
    split_w<<<512, 256>>>(W_theta, Wth, Wtm, Wtl, C1 * CIN);
    split_w<<<512, 256>>>(W_phi,   Wph, Wpm, Wpl, C1 * CIN);
    split_w<<<512, 256>>>(W_g,     Wgh, Wgm, nullptr, C1 * CIN);
    split_w<<<512, 256>>>(W2,      W2h, W2m, nullptr, CIN * C1);
    split_w<<<256, 256>>>(W3,      W3h, W3m, nullptr, DD * CIN);

    // theta/phi (x6) -> fp32 transposed layout (N, C1); g (x3) -> bf16 h/m direct
    mma_gemm<6><<<dim3(2, 576, 1), 256>>>(
        Xh, Xm, Xl, CIN, 0, Wth, Wtm, Wtl, CIN, 0,
        Tt, nullptr, nullptr, C1, 0, b_theta, nullptr, nullptr, nullptr, CIN, 1, 4);
    mma_gemm<6><<<dim3(2, 576, 1), 256>>>(
        Xh, Xm, Xl, CIN, 0, Wph, Wpm, Wpl, CIN, 0,
        Pt, nullptr, nullptr, C1, 0, b_phi, nullptr, nullptr, nullptr, CIN, 1, 4);
    mma_gemm<3><<<dim3(2, 576, 1), 256>>>(
        Xh, Xm, nullptr, CIN, 0, Wgh, Wgm, nullptr, CIN, 0,
        nullptr, Gh, Gm, C1, 0, b_g, nullptr, nullptr, nullptr, CIN, 1, 4);

    // transpose theta/phi to (B, C1, NN) + split h/m/l
    tsplit<<<dim3(8, 288, BB), dim3(32, 8)>>>(Tt, Th, Tm, Tl, NN, C1);
    tsplit<<<dim3(8, 288, BB), dim3(32, 8)>>>(Pt, Ph, Pm, Pl, NN, C1);

    // f = theta @ phi^T (x6, split-K = FS chunks of 1024)
    mma_gemm<6><<<dim3(2, 2, BB * FS), 256>>>(
        Th, Tm, Tl, NN, (long)C1 * NN, Ph, Pm, Pl, NN, (long)C1 * NN,
        Fp, nullptr, nullptr, C1, (long)C1 * C1, nullptr, nullptr, nullptr, nullptr,
        NN / FS, FS, 5);
    softmax9<<<BB * C1, 256>>>(Fp, Fh, Fm);

    // y[n, c] = sum_d g[n, d] * f[c, d] per batch (x3)
    mma_gemm<3><<<dim3(2, 72, BB), 256>>>(
        Gh, Gm, nullptr, C1, (long)NN * C1, Fh, Fm, nullptr, C1, (long)C1 * C1,
        nullptr, Yh, Ym, C1, (long)NN * C1, nullptr, nullptr, nullptr, nullptr, C1, 1, 3);

    // z = y @ W2^T + b2 + X (x3)
    mma_gemm<3><<<dim3(4, 576, 1), 256>>>(
        Yh, Ym, nullptr, C1, 0, W2h, W2m, nullptr, C1, 0,
        Zt, Zh, Zm, CIN, 0, b2, Xh, Xm, Xl, C1, 1, 3);

    // z_ = z @ W3^T + b3 (x3)
    mma_gemm<3><<<dim3(1, 576, 1), 256>>>(
        Zh, Zm, nullptr, CIN, 0, W3h, W3m, nullptr, CIN, 0,
        ZDt, nullptr, nullptr, DD, 0, b3, nullptr, nullptr, nullptr, CIN, 1, 4);

    encode_kernel<<<dim3(96, BB), 256>>>(ZDt, codewords, scale, Eacc, Asum);
    bn_es_kernel<<<KK, 256>>>(Eacc, Asum, codewords, Es);
    gamma_kernel<<<(BB * CIN) / 256, 256>>>(Es, W_fc, b_fc, gamB);
    tscale_out<<<dim3(288, 16, BB), dim3(32, 8)>>>(Zt, gamB, (float*)d_out);
}

// round 7
// speedup vs baseline: 1.1344x; 1.0974x over previous
#include <cuda_runtime.h>
#include <cuda_bf16.h>
#include <math.h>
#include <stdint.h>

#define BB 8
#define CIN 512
#define C1 256
#define DD 128
#define KK 32
#define NN 9216
#define ROWS (BB*NN)
#define FS 9
typedef __nv_bfloat16 bf16;
typedef unsigned int u32;

// ------------- scratch (device globals) -------------
__device__ bf16 g_Xh[ROWS*CIN], g_Xm[ROWS*CIN], g_Xl[ROWS*CIN];
__device__ bf16 g_Wth[C1*CIN], g_Wtm[C1*CIN], g_Wtl[C1*CIN];
__device__ bf16 g_Wph[C1*CIN], g_Wpm[C1*CIN], g_Wpl[C1*CIN];
__device__ bf16 g_Wgh[C1*CIN], g_Wgm[C1*CIN];
__device__ bf16 g_W2h[CIN*C1], g_W2m[CIN*C1];
__device__ bf16 g_W3h[DD*CIN], g_W3m[DD*CIN];
__device__ bf16 g_Th[C1*ROWS], g_Tm[C1*ROWS], g_Tl[C1*ROWS];   // theta (C1, B*N)
__device__ bf16 g_Phh[C1*ROWS], g_Pmm[C1*ROWS], g_Pll[C1*ROWS]; // phi
__device__ bf16 g_Gh[ROWS*C1], g_Gm[ROWS*C1];                   // g (N, C1)
__device__ float g_Fp[FS*BB*C1*C1];
__device__ bf16 g_Fh[BB*C1*C1], g_Fm[BB*C1*C1];
__device__ bf16 g_Yh[ROWS*C1], g_Ym[ROWS*C1];
__device__ float g_Zt[ROWS*CIN];
__device__ bf16 g_Zh[ROWS*CIN], g_Zm[ROWS*CIN];
__device__ float g_ZDt[ROWS*DD];
__device__ float g_Eacc[BB*KK*DD], g_Asum[BB*KK], g_Es[BB*DD], g_gam[BB*CIN];

// ------------- helpers -------------
__device__ __forceinline__ u32 smem_u32(const void* p) {
    u32 a;
    asm("{ .reg .u64 t; cvta.to.shared.u64 t, %1; cvt.u32.u64 %0, t; }" : "=r"(a) : "l"(p));
    return a;
}
__device__ __forceinline__ void cp16(u32 d, const void* s) {
    asm volatile("cp.async.cg.shared.global [%0], [%1], 16;" :: "r"(d), "l"(s));
}
__device__ __forceinline__ void cp_commit() { asm volatile("cp.async.commit_group;" ::: "memory"); }
template<int N> __device__ __forceinline__ void cp_waitg() {
    asm volatile("cp.async.wait_group %0;" :: "n"(N) : "memory");
}
__device__ __forceinline__ void ldm_x4(u32* r, u32 addr) {
    asm volatile("ldmatrix.sync.aligned.m8n8.x4.shared.b16 {%0,%1,%2,%3}, [%4];"
        : "=r"(r[0]), "=r"(r[1]), "=r"(r[2]), "=r"(r[3]) : "r"(addr));
}
__device__ __forceinline__ void mma16816(float* d, const u32* a, const u32* b) {
    asm volatile(
        "mma.sync.aligned.m16n8k16.row.col.f32.bf16.bf16.f32 "
        "{%0,%1,%2,%3}, {%4,%5,%6,%7}, {%8,%9}, {%0,%1,%2,%3};"
        : "+f"(d[0]), "+f"(d[1]), "+f"(d[2]), "+f"(d[3])
        : "r"(a[0]), "r"(a[1]), "r"(a[2]), "r"(a[3]), "r"(b[0]), "r"(b[1]));
}
__device__ __forceinline__ float2 rd2bf(const bf16* p, long i) {
    u32 v = *(const u32*)(p + i);
    __nv_bfloat162 b = *(__nv_bfloat162*)&v;
    return make_float2(__bfloat162float(b.x), __bfloat162float(b.y));
}
__device__ __forceinline__ void st2bf(bf16* p, long i, float a, float b_) {
    __nv_bfloat162 v(__float2bfloat16(a), __float2bfloat16(b_));
    *(u32*)(p + i) = *(u32*)&v;
}

// ============ mma.sync bf16-split GEMM, cp.async 2-stage, BK=64 ============
// C[z; m, n] = sum over products of A_part[b; m, k] * B_part[b; n, k], K-major.
// CTA tile 128x128, 8 warps (2m x 4n), warp tile 64x32.
// smem: stage s at s*36864: A (128x144B), then B at +18432.
#define PITCH 144
#define ASTG 18432
#define STG2 36864
#define SMEMSZ 73728

template<int NPROD>
__global__ __launch_bounds__(256, 2) void mma_gemm(
    const bf16* __restrict__ Ah, const bf16* __restrict__ Am, const bf16* __restrict__ Al,
    int lda, long sAb,
    const bf16* __restrict__ Bh, const bf16* __restrict__ Bm, const bf16* __restrict__ Bl,
    int ldb, long sBb,
    float* __restrict__ C, bf16* __restrict__ Ch, bf16* __restrict__ Cm, bf16* __restrict__ Cl,
    int ldc, long sCz,
    const float* __restrict__ biasC, const float* __restrict__ biasR,
    const bf16* __restrict__ Rh, const bf16* __restrict__ Rm, const bf16* __restrict__ Rl,
    int KS, int S, int KCL)  // KCL = log2(KS/64)
{
    extern __shared__ __align__(16) char smem[];
    const u32 sbase = smem_u32(smem);

    const int tid = threadIdx.x, lane = tid & 31, wid = tid >> 5;
    const int wm = wid & 1, wn = wid >> 1;
    const int z = blockIdx.z, b = z / S, s = z % S;
    const long m0 = (long)blockIdx.y * 128;
    const int n0 = blockIdx.x * 128;

    const long abase = (long)b * sAb + m0 * lda + (long)s * KS;
    const long bbase = (long)b * sBb + (long)n0 * ldb + (long)s * KS;

    const int lrow = tid >> 1, lq = tid & 1;   // 128 rows, 2 thr/row, 64B each
    const int NCH = NPROD << KCL;
    const int kmask = (1 << KCL) - 1;

    float acc[4][4][4];
#pragma unroll
    for (int i = 0; i < 4; i++)
#pragma unroll
        for (int j = 0; j < 4; j++)
#pragma unroll
            for (int r = 0; r < 4; r++) acc[i][j][r] = 0.f;

    auto issue = [&](int c) {
        int p = c >> KCL, k0 = (c & kmask) << 6;
        int pa_, pb_;
        if (NPROD == 6) {
            pa_ = (p == 2 || p == 3) ? 1 : (p == 5 ? 2 : 0);
            pb_ = (p == 1 || p == 3) ? 1 : (p == 4 ? 2 : 0);
        } else {
            pa_ = (p == 2) ? 1 : 0;
            pb_ = (p == 1) ? 1 : 0;
        }
        const bf16* ag = (pa_ == 0 ? Ah : (pa_ == 1 ? Am : Al)) + abase + k0;
        const bf16* bg = (pb_ == 0 ? Bh : (pb_ == 1 ? Bm : Bl)) + bbase + k0;
        u32 sa = sbase + (c & 1) * STG2 + lrow * PITCH + lq * 64;
        u32 sb = sa + ASTG;
        const bf16* ap = ag + (long)lrow * lda + lq * 32;
        const bf16* bp = bg + (long)lrow * ldb + lq * 32;
#pragma unroll
        for (int i = 0; i < 4; i++) {
            cp16(sa + i * 16, ap + i * 8);
            cp16(sb + i * 16, bp + i * 8);
        }
        cp_commit();
    };

    // ldmatrix lane offsets (pitch 144)
    u32 aoff[4], boff[2];
#pragma unroll
    for (int t = 0; t < 4; t++)
        aoff[t] = (u32)((wm * 64 + t * 16 + (lane & 15)) * PITCH + (lane >> 4) * 16);
#pragma unroll
    for (int u = 0; u < 2; u++)
        boff[u] = (u32)((wn * 32 + u * 16 + (lane & 7) + (lane >> 4) * 8) * PITCH
                        + ((lane >> 3) & 1) * 16);

    issue(0);
    for (int c = 0; c < NCH; c++) {
        int st = c & 1;
        if (c + 1 < NCH) { issue(c + 1); cp_waitg<1>(); }
        else cp_waitg<0>();
        __syncthreads();
        u32 sa = sbase + st * STG2;
        u32 sb = sa + ASTG;
#pragma unroll
        for (int kk = 0; kk < 4; kk++) {
            u32 af[4][4], bfr[2][4];
#pragma unroll
            for (int t = 0; t < 4; t++) ldm_x4(af[t], sa + aoff[t] + kk * 32);
#pragma unroll
            for (int u = 0; u < 2; u++) ldm_x4(bfr[u], sb + boff[u] + kk * 32);
#pragma unroll
            for (int mi = 0; mi < 4; mi++)
#pragma unroll
                for (int ni = 0; ni < 4; ni++)
                    mma16816(acc[mi][ni], af[mi], &bfr[ni >> 1][(ni & 1) * 2]);
        }
        __syncthreads();
    }

    // ---- epilogue ----
    const int mrow = lane >> 2, nc2 = (lane & 3) * 2;
#pragma unroll
    for (int mi = 0; mi < 4; mi++) {
#pragma unroll
        for (int rp = 0; rp < 2; rp++) {
            long row = m0 + wm * 64 + mi * 16 + mrow + rp * 8;
            long rowoff = (long)z * sCz + row * ldc;
            float br = biasR ? biasR[row] : 0.f;
#pragma unroll
            for (int ni = 0; ni < 4; ni++) {
                int col = n0 + wn * 32 + ni * 8 + nc2;
                float v0 = acc[mi][ni][rp * 2 + 0] + br;
                float v1 = acc[mi][ni][rp * 2 + 1] + br;
                if (biasC) { v0 += biasC[col]; v1 += biasC[col + 1]; }
                if (Rh) {
                    float2 h = rd2bf(Rh, rowoff + col);
                    float2 m = rd2bf(Rm, rowoff + col);
                    float2 l = rd2bf(Rl, rowoff + col);
                    v0 += h.x + m.x + l.x;
                    v1 += h.y + m.y + l.y;
                }
                if (C) *(float2*)&C[rowoff + col] = make_float2(v0, v1);
                if (Ch) {
                    float h0 = __bfloat162float(__float2bfloat16(v0));
                    float h1 = __bfloat162float(__float2bfloat16(v1));
                    st2bf(Ch, rowoff + col, v0, v1);
                    float r0 = v0 - h0, r1 = v1 - h1;
                    st2bf(Cm, rowoff + col, r0, r1);
                    if (Cl) {
                        float m0f = __bfloat162float(__float2bfloat16(r0));
                        float m1f = __bfloat162float(__float2bfloat16(r1));
                        st2bf(Cl, rowoff + col, r0 - m0f, r1 - m1f);
                    }
                }
            }
        }
    }
}

// ------------- tiled transpose + 3-way bf16 split (X only) -------------
__global__ void tsplit(const float* __restrict__ src, bf16* __restrict__ h,
                       bf16* __restrict__ m, bf16* __restrict__ l, int R, int C)
{
    __shared__ float ts[32][33];
    int b = blockIdx.z;
    long o = (long)b * R * C;
    int c0 = blockIdx.x * 32, r0 = blockIdx.y * 32;
    int tx = threadIdx.x, ty = threadIdx.y;
#pragma unroll
    for (int i = 0; i < 4; i++)
        ts[ty + i * 8][tx] = src[o + (long)(r0 + ty + i * 8) * C + c0 + tx];
    __syncthreads();
#pragma unroll
    for (int i = 0; i < 4; i++) {
        int c = c0 + ty + i * 8;
        float v = ts[tx][ty + i * 8];
        long idx = o + (long)c * R + r0 + tx;
        bf16 hh = __float2bfloat16(v);
        float r1 = v - __bfloat162float(hh);
        bf16 mm = __float2bfloat16(r1);
        h[idx] = hh; m[idx] = mm;
        l[idx] = __float2bfloat16(r1 - __bfloat162float(mm));
    }
}

// ------------- all weight splits in one launch -------------
__global__ void split_all(const float* __restrict__ Wt, const float* __restrict__ Wp,
                          const float* __restrict__ Wg, const float* __restrict__ W2,
                          const float* __restrict__ W3)
{
    int i = blockIdx.x * 256 + threadIdx.x;   // grid 512 -> 131072
    if (i < C1 * CIN) {
        float v = Wt[i];
        bf16 h = __float2bfloat16(v); float r1 = v - __bfloat162float(h);
        bf16 m = __float2bfloat16(r1);
        g_Wth[i] = h; g_Wtm[i] = m; g_Wtl[i] = __float2bfloat16(r1 - __bfloat162float(m));
        v = Wp[i];
        h = __float2bfloat16(v); r1 = v - __bfloat162float(h);
        m = __float2bfloat16(r1);
        g_Wph[i] = h; g_Wpm[i] = m; g_Wpl[i] = __float2bfloat16(r1 - __bfloat162float(m));
        v = Wg[i];
        h = __float2bfloat16(v);
        g_Wgh[i] = h; g_Wgm[i] = __float2bfloat16(v - __bfloat162float(h));
        v = W2[i];
        h = __float2bfloat16(v);
        g_W2h[i] = h; g_W2m[i] = __float2bfloat16(v - __bfloat162float(h));
    }
    if (i < DD * CIN) {
        float v = W3[i];
        bf16 h = __float2bfloat16(v);
        g_W3h[i] = h; g_W3m[i] = __float2bfloat16(v - __bfloat162float(h));
    }
}

// ------------- softmax over f (reduce FS partials), emit bf16 h/m -------------
__global__ void softmax9(const float* __restrict__ Fp, bf16* __restrict__ Fh, bf16* __restrict__ Fm)
{
    int row = blockIdx.x, t = threadIdx.x;
    int b = row >> 8, c = row & 255;
    long base = (long)(b * FS) * 65536 + c * 256 + t;
    float v = 0.f;
#pragma unroll
    for (int s2 = 0; s2 < FS; s2++) v += Fp[base + (long)s2 * 65536];
    __shared__ float sh[256];
    sh[t] = v; __syncthreads();
    for (int o = 128; o; o >>= 1) { if (t < o) sh[t] = fmaxf(sh[t], sh[t + o]); __syncthreads(); }
    float mx = sh[0]; __syncthreads();
    float e = expf(v - mx);
    sh[t] = e; __syncthreads();
    for (int o = 128; o; o >>= 1) { if (t < o) sh[t] += sh[t + o]; __syncthreads(); }
    float r = e / sh[0];
    long o2 = (long)b * 65536 + c * 256 + t;
    bf16 h = __float2bfloat16(r);
    Fh[o2] = h;
    Fm[o2] = __float2bfloat16(r - __bfloat162float(h));
}

// ------------- zero accumulators -------------
__global__ void zero_kernel() {
    int i = blockIdx.x * blockDim.x + threadIdx.x;
    if (i < BB * KK * DD) g_Eacc[i] = 0.f;
    if (i < BB * KK)      g_Asum[i] = 0.f;
    if (i < BB * DD)      g_Es[i]   = 0.f;
}

// ------------- fused dist -> softmax(A) -> E accumulation -------------
__global__ __launch_bounds__(256) void encode_kernel(
    const float* __restrict__ ZDt,
    const float* __restrict__ codewords, const float* __restrict__ scale,
    float* __restrict__ Eacc, float* __restrict__ Asum)
{
    int b = blockIdx.y;
    __shared__ float cs[KK][DD + 1];
    __shared__ float cn[KK], sc[KK];
    __shared__ float xs[DD][33];
    __shared__ float Ash[8][KK];
    int tid = threadIdx.x, lane = tid & 31, wid = tid >> 5;

    for (int i = tid; i < KK * DD; i += 256) cs[i >> 7][i & 127] = codewords[i];
    if (tid < KK) sc[tid] = scale[tid];
    __syncthreads();
    if (tid < KK) {
        float s = 0.f;
        for (int d = 0; d < DD; d++) { float c = cs[tid][d]; s += c * c; }
        cn[tid] = s;
    }
    __syncthreads();

    float ereg[16];
#pragma unroll
    for (int i = 0; i < 16; i++) ereg[i] = 0.f;
    float asum_local = 0.f;
    int myk = tid >> 3, myd0 = tid & 7;

    for (int t = blockIdx.x; t < NN / 32; t += gridDim.x) {
        int n0 = t * 32;
#pragma unroll
        for (int r = 0; r < 4; r++) {
            int idx = r * 256 + tid;
            int n = idx >> 5, d4 = (idx & 31) * 4;
            float4 v = *(const float4*)(ZDt + ((long)b * NN + n0 + n) * DD + d4);
            xs[d4][n] = v.x; xs[d4 + 1][n] = v.y; xs[d4 + 2][n] = v.z; xs[d4 + 3][n] = v.w;
        }
        __syncthreads();
        for (int round = 0; round < 4; round++) {
            int n = round * 8 + wid;
            float xx = 0.f;
            for (int d = lane; d < DD; d += 32) { float x = xs[d][n]; xx += x * x; }
            for (int o = 16; o; o >>= 1) xx += __shfl_xor_sync(0xffffffffu, xx, o);
            float dot = 0.f;
#pragma unroll 8
            for (int d = 0; d < DD; d++) dot += xs[d][n] * cs[lane][d];
            float s = sc[lane] * (xx - 2.f * dot + cn[lane]);
            float mx = s;
            for (int o = 16; o; o >>= 1) mx = fmaxf(mx, __shfl_xor_sync(0xffffffffu, mx, o));
            float e = __expf(s - mx);
            float ssum = e;
            for (int o = 16; o; o >>= 1) ssum += __shfl_xor_sync(0xffffffffu, ssum, o);
            float a = e / ssum;
            Ash[wid][lane] = a;
            asum_local += a;
            __syncthreads();
#pragma unroll
            for (int nn2 = 0; nn2 < 8; nn2++) {
                float av = Ash[nn2][myk];
                int ncol = round * 8 + nn2;
#pragma unroll
                for (int i = 0; i < 16; i++)
                    ereg[i] += av * xs[myd0 + 8 * i][ncol];
            }
            __syncthreads();
        }
    }
#pragma unroll
    for (int i = 0; i < 16; i++)
        atomicAdd(&Eacc[((long)b * KK + myk) * DD + myd0 + 8 * i], ereg[i]);
    atomicAdd(&Asum[b * KK + lane], asum_local);
}

// ------------- BN over K + Es -------------
__global__ void bn_es_kernel(const float* __restrict__ Eacc, const float* __restrict__ Asum,
                             const float* __restrict__ codewords, float* __restrict__ Es)
{
    int k = blockIdx.x, tid = threadIdx.x;
    __shared__ double shs[256], shs2[256];
    float vals[4];
    double s = 0.0, s2 = 0.0;
#pragma unroll
    for (int i = 0; i < 4; i++) {
        int idx = tid + i * 256;
        int b = idx >> 7, d = idx & 127;
        float v = Eacc[((long)b * KK + k) * DD + d] - Asum[b * KK + k] * codewords[k * DD + d];
        vals[i] = v; s += v; s2 += (double)v * v;
    }
    shs[tid] = s; shs2[tid] = s2; __syncthreads();
    for (int o = 128; o; o >>= 1) {
        if (tid < o) { shs[tid] += shs[tid + o]; shs2[tid] += shs2[tid + o]; }
        __syncthreads();
    }
    double mean = shs[0] / 1024.0;
    double var = shs2[0] / 1024.0 - mean * mean;
    float inv = rsqrtf((float)var + 1e-5f);
    float mf = (float)mean;
#pragma unroll
    for (int i = 0; i < 4; i++) {
        int idx = tid + i * 256;
        int b = idx >> 7, d = idx & 127;
        float e = (vals[i] - mf) * inv;
        if (e > 0.f) atomicAdd(&Es[b * DD + d], e);
    }
}

// ------------- gamma = sigmoid(Es @ W_fc^T + b_fc) -------------
__global__ void gamma_kernel(const float* __restrict__ Es, const float* __restrict__ W_fc,
                             const float* __restrict__ b_fc, float* __restrict__ gam)
{
    int idx = blockIdx.x * blockDim.x + threadIdx.x;
    int b = idx / CIN, c = idx % CIN;
    float s = b_fc[c];
    for (int d = 0; d < DD; d++) s += Es[b * DD + d] * W_fc[c * DD + d];
    gam[idx] = 1.f / (1.f + expf(-s));
}

// ------------- transpose back + gamma scale -> output (B, C, N) -------------
__global__ void tscale_out(const float* __restrict__ Zt, const float* __restrict__ gam,
                           float* __restrict__ out)
{
    __shared__ float ts[32][33];
    int b = blockIdx.z;
    int n0 = blockIdx.x * 32, c0 = blockIdx.y * 32;
    int tx = threadIdx.x, ty = threadIdx.y;
#pragma unroll
    for (int i = 0; i < 4; i++)
        ts[ty + i * 8][tx] = Zt[((long)b * NN + n0 + ty + i * 8) * CIN + c0 + tx];
    __syncthreads();
#pragma unroll
    for (int i = 0; i < 4; i++) {
        int c = c0 + ty + i * 8;
        out[((long)b * CIN + c) * NN + n0 + tx] = ts[tx][ty + i * 8] * gam[b * CIN + c];
    }
}

// ------------- launch -------------
#define GA(T, p, s) T* p; cudaGetSymbolAddress((void**)&p, s)

extern "C" void kernel_launch(void* const* d_in, const int* in_sizes, int n_in,
                              void* d_out, int out_size)
{
    const float* X        = (const float*)d_in[0];
    const float* W_theta  = (const float*)d_in[1];
    const float* b_theta  = (const float*)d_in[2];
    const float* W_phi    = (const float*)d_in[3];
    const float* b_phi    = (const float*)d_in[4];
    const float* W_g      = (const float*)d_in[5];
    const float* b_g      = (const float*)d_in[6];
    const float* W2       = (const float*)d_in[7];
    const float* b2       = (const float*)d_in[8];
    const float* W3       = (const float*)d_in[9];
    const float* b3       = (const float*)d_in[10];
    const float* codewords= (const float*)d_in[11];
    const float* scale    = (const float*)d_in[12];
    const float* W_fc     = (const float*)d_in[13];
    const float* b_fc     = (const float*)d_in[14];

    GA(bf16, Xh, g_Xh); GA(bf16, Xm, g_Xm); GA(bf16, Xl, g_Xl);
    GA(bf16, Wth, g_Wth); GA(bf16, Wtm, g_Wtm); GA(bf16, Wtl, g_Wtl);
    GA(bf16, Wph, g_Wph); GA(bf16, Wpm, g_Wpm); GA(bf16, Wpl, g_Wpl);
    GA(bf16, Wgh, g_Wgh); GA(bf16, Wgm, g_Wgm);
    GA(bf16, W2h, g_W2h); GA(bf16, W2m, g_W2m);
    GA(bf16, W3h, g_W3h); GA(bf16, W3m, g_W3m);
    GA(bf16, Th, g_Th); GA(bf16, Tm, g_Tm); GA(bf16, Tl, g_Tl);
    GA(bf16, Ph, g_Phh); GA(bf16, Pm, g_Pmm); GA(bf16, Pl, g_Pll);
    GA(bf16, Gh, g_Gh); GA(bf16, Gm, g_Gm);
    GA(float, Fp, g_Fp);
    GA(bf16, Fh, g_Fh); GA(bf16, Fm, g_Fm);
    GA(bf16, Yh, g_Yh); GA(bf16, Ym, g_Ym);
    GA(float, Zt, g_Zt);
    GA(bf16, Zh, g_Zh); GA(bf16, Zm, g_Zm);
    GA(float, ZDt, g_ZDt);
    GA(float, Eacc, g_Eacc); GA(float, Asum, g_Asum);
    GA(float, Es, g_Es); GA(float, gamB, g_gam);

    cudaFuncSetAttribute(mma_gemm<6>, cudaFuncAttributeMaxDynamicSharedMemorySize, SMEMSZ);
    cudaFuncSetAttribute(mma_gemm<3>, cudaFuncAttributeMaxDynamicSharedMemorySize, SMEMSZ);

    // 1: zero, 2: tsplit X, 3: split_all, 4: phi, 5: g, 6: theta (ncu -s 5 -c 1 target)
    zero_kernel<<<128, 256>>>();
    tsplit<<<dim3(288, 16, BB), dim3(32, 8)>>>(X, Xh, Xm, Xl, CIN, NN);
    split_all<<<512, 256>>>(W_theta, W_phi, W_g, W2, W3);

    // phi: (C1 x 73728) = W_phi @ X^T, x6, output bf16 parts directly (row-bias)
    mma_gemm<6><<<dim3(576, 2, 1), 256, SMEMSZ>>>(
        Wph, Wpm, Wpl, CIN, 0, Xh, Xm, Xl, CIN, 0,
        nullptr, Ph, Pm, Pl, ROWS, 0, nullptr, b_phi, nullptr, nullptr, nullptr,
        CIN, 1, 3);
    // g: (73728 x C1) = X^T @ W_g^T, x3 (col-bias)
    mma_gemm<3><<<dim3(2, 576, 1), 256, SMEMSZ>>>(
        Xh, Xm, nullptr, CIN, 0, Wgh, Wgm, nullptr, CIN, 0,
        nullptr, Gh, Gm, nullptr, C1, 0, b_g, nullptr, nullptr, nullptr, nullptr,
        CIN, 1, 3);
    // theta: like phi
    mma_gemm<6><<<dim3(576, 2, 1), 256, SMEMSZ>>>(
        Wth, Wtm, Wtl, CIN, 0, Xh, Xm, Xl, CIN, 0,
        nullptr, Th, Tm, Tl, ROWS, 0, nullptr, b_theta, nullptr, nullptr, nullptr,
        CIN, 1, 3);

    // f = theta @ phi^T (x6, split-K = FS chunks of 1024)
    mma_gemm<6><<<dim3(2, 2, BB * FS), 256, SMEMSZ>>>(
        Th, Tm, Tl, ROWS, NN, Ph, Pm, Pl, ROWS, NN,
        Fp, nullptr, nullptr, nullptr, C1, (long)C1 * C1,
        nullptr, nullptr, nullptr, nullptr, nullptr, NN / FS, FS, 4);
    softmax9<<<BB * C1, 256>>>(Fp, Fh, Fm);

    // y[n, c] = sum_d g[n, d] * f[c, d] per batch (x3)
    mma_gemm<3><<<dim3(2, 72, BB), 256, SMEMSZ>>>(
        Gh, Gm, nullptr, C1, (long)NN * C1, Fh, Fm, nullptr, C1, (long)C1 * C1,
        nullptr, Yh, Ym, nullptr, C1, (long)NN * C1,
        nullptr, nullptr, nullptr, nullptr, nullptr, C1, 1, 2);

    // z = y @ W2^T + b2 + X (x3): fp32 + bf16 h/m
    mma_gemm<3><<<dim3(4, 576, 1), 256, SMEMSZ>>>(
        Yh, Ym, nullptr, C1, 0, W2h, W2m, nullptr, C1, 0,
        Zt, Zh, Zm, nullptr, CIN, 0, b2, nullptr, Xh, Xm, Xl, C1, 1, 2);

    // z_ = z @ W3^T + b3 (x3)
    mma_gemm<3><<<dim3(1, 576, 1), 256, SMEMSZ>>>(
        Zh, Zm, nullptr, CIN, 0, W3h, W3m, nullptr, CIN, 0,
        ZDt, nullptr, nullptr, nullptr, DD, 0, b3, nullptr, nullptr, nullptr, nullptr,
        CIN, 1, 3);

    encode_kernel<<<dim3(96, BB), 256>>>(ZDt, codewords, scale, Eacc, Asum);
    bn_es_kernel<<<KK, 256>>>(Eacc, Asum, codewords, Es);
    gamma_kernel<<<(BB * CIN) / 256, 256>>>(Es, W_fc, b_fc, gamB);
    tscale_out<<<dim3(288, 16, BB), dim3(32, 8)>>>(Zt, gamB, (float*)d_out);
}

// round 8
// speedup vs baseline: 1.6465x; 1.4514x over previous
#include <cuda_runtime.h>
#include <cuda_bf16.h>
#include <math.h>
#include <stdint.h>

#define BB 8
#define CIN 512
#define C1 256
#define DD 128
#define KK 32
#define NN 9216
#define ROWS (BB*NN)
#define FS 9
typedef __nv_bfloat16 bf16;
typedef unsigned int u32;

// ------------- scratch (device globals) -------------
__device__ bf16 g_Xh[ROWS*CIN], g_Xm[ROWS*CIN], g_Xl[ROWS*CIN];
__device__ bf16 g_Wth[C1*CIN], g_Wtm[C1*CIN], g_Wtl[C1*CIN];
__device__ bf16 g_Wph[C1*CIN], g_Wpm[C1*CIN], g_Wpl[C1*CIN];
__device__ bf16 g_Wgh[C1*CIN], g_Wgm[C1*CIN];
__device__ bf16 g_W2h[CIN*C1], g_W2m[CIN*C1];
__device__ bf16 g_W3h[DD*CIN], g_W3m[DD*CIN];
__device__ bf16 g_Th[C1*ROWS], g_Tm[C1*ROWS], g_Tl[C1*ROWS];   // theta (C1, B*N)
__device__ bf16 g_Phh[C1*ROWS], g_Pmm[C1*ROWS], g_Pll[C1*ROWS]; // phi
__device__ bf16 g_Gh[ROWS*C1], g_Gm[ROWS*C1];                   // g (N, C1)
__device__ float g_Fp[FS*BB*C1*C1];
__device__ bf16 g_Fh[BB*C1*C1], g_Fm[BB*C1*C1];
__device__ bf16 g_Yh[ROWS*C1], g_Ym[ROWS*C1];
__device__ float g_Zt[ROWS*CIN];
__device__ bf16 g_Zh[ROWS*CIN], g_Zm[ROWS*CIN];
__device__ float g_ZDt[ROWS*DD];
__device__ float g_Eacc[BB*KK*DD], g_Asum[BB*KK], g_Es[BB*DD], g_gam[BB*CIN];

// ------------- helpers -------------
__device__ __forceinline__ u32 smem_u32(const void* p) {
    u32 a;
    asm("{ .reg .u64 t; cvta.to.shared.u64 t, %1; cvt.u32.u64 %0, t; }" : "=r"(a) : "l"(p));
    return a;
}
__device__ __forceinline__ void cp16(u32 d, const void* s) {
    asm volatile("cp.async.cg.shared.global [%0], [%1], 16;" :: "r"(d), "l"(s));
}
__device__ __forceinline__ void cp_commit() { asm volatile("cp.async.commit_group;" ::: "memory"); }
template<int N> __device__ __forceinline__ void cp_waitg() {
    asm volatile("cp.async.wait_group %0;" :: "n"(N) : "memory");
}
__device__ __forceinline__ void ldm_x4(u32* r, u32 addr) {
    asm volatile("ldmatrix.sync.aligned.m8n8.x4.shared.b16 {%0,%1,%2,%3}, [%4];"
        : "=r"(r[0]), "=r"(r[1]), "=r"(r[2]), "=r"(r[3]) : "r"(addr));
}
__device__ __forceinline__ void mma16816(float* d, const u32* a, const u32* b) {
    asm volatile(
        "mma.sync.aligned.m16n8k16.row.col.f32.bf16.bf16.f32 "
        "{%0,%1,%2,%3}, {%4,%5,%6,%7}, {%8,%9}, {%0,%1,%2,%3};"
        : "+f"(d[0]), "+f"(d[1]), "+f"(d[2]), "+f"(d[3])
        : "r"(a[0]), "r"(a[1]), "r"(a[2]), "r"(a[3]), "r"(b[0]), "r"(b[1]));
}
__device__ __forceinline__ float2 rd2bf(const bf16* p, long i) {
    u32 v = *(const u32*)(p + i);
    __nv_bfloat162 b = *(__nv_bfloat162*)&v;
    return make_float2(__bfloat162float(b.x), __bfloat162float(b.y));
}
__device__ __forceinline__ void st2bf(bf16* p, long i, float a, float b_) {
    __nv_bfloat162 v(__float2bfloat16(a), __float2bfloat16(b_));
    *(u32*)(p + i) = *(u32*)&v;
}

// ============ mma.sync bf16-split GEMM, product-shared tiles, BK=32 ============
// C[z; m, n] = sum over triangular products A_pa * B_pb (pa+pb<NB), K-major.
// CTA tile 128x128, 8 warps (2m x 4n), warp tile 64x32.
// smem tile: 128 rows x 64B, XOR swizzle chunk j -> j ^ ((row>>1)&3). 8KB/tile.
template<int NPROD>
__global__ __launch_bounds__(256, 2) void mma_gemm(
    const bf16* __restrict__ Ah, const bf16* __restrict__ Am, const bf16* __restrict__ Al,
    int lda, long sAb,
    const bf16* __restrict__ Bh, const bf16* __restrict__ Bm, const bf16* __restrict__ Bl,
    int ldb, long sBb,
    float* __restrict__ C, bf16* __restrict__ Ch, bf16* __restrict__ Cm, bf16* __restrict__ Cl,
    int ldc, long sCz,
    const float* __restrict__ biasC, const float* __restrict__ biasR,
    const bf16* __restrict__ Rh, const bf16* __restrict__ Rm, const bf16* __restrict__ Rl,
    int NCH, int S)   // NCH = K/32 chunks
{
    constexpr int NA = (NPROD == 6) ? 3 : 2;
    constexpr int NB = NA;
    constexpr int STAGE = (NA + NB) * 8192;

    extern __shared__ __align__(16) char smem[];
    const u32 sbase = smem_u32(smem);

    const int tid = threadIdx.x, lane = tid & 31, wid = tid >> 5;
    const int wm = wid & 1, wn = wid >> 1;
    const int z = blockIdx.z, b = z / S, s = z % S;
    const long m0 = (long)blockIdx.y * 128;
    const int n0 = blockIdx.x * 128;
    const int KS = NCH * 32;

    const long abase = (long)b * sAb + m0 * lda + (long)s * KS;
    const long bbase = (long)b * sBb + (long)n0 * ldb + (long)s * KS;

    const bf16* APT[3] = {Ah, Am, Al};
    const bf16* BPT[3] = {Bh, Bm, Bl};

    float acc[4][4][4];
#pragma unroll
    for (int i = 0; i < 4; i++)
#pragma unroll
        for (int j = 0; j < 4; j++)
#pragma unroll
            for (int r = 0; r < 4; r++) acc[i][j][r] = 0.f;

    const int row2 = tid >> 1, lq = tid & 1;
    const int sw = (row2 >> 1) & 3;
    const u32 c0off = (u32)(row2 * 64 + (((lq * 2 + 0) ^ sw) << 4));
    const u32 c1off = (u32)(row2 * 64 + (((lq * 2 + 1) ^ sw) << 4));

    auto issue = [&](int c) {
        int k0 = c * 32;
        u32 sd = sbase + (c & 1) * STAGE;
#pragma unroll
        for (int p = 0; p < NA; p++) {
            const bf16* ap = APT[p] + abase + k0 + (long)row2 * lda + lq * 16;
            cp16(sd + p * 8192 + c0off, ap);
            cp16(sd + p * 8192 + c1off, ap + 8);
        }
#pragma unroll
        for (int p = 0; p < NB; p++) {
            const bf16* bp = BPT[p] + bbase + k0 + (long)row2 * ldb + lq * 16;
            cp16(sd + (NA + p) * 8192 + c0off, bp);
            cp16(sd + (NA + p) * 8192 + c1off, bp + 8);
        }
        cp_commit();
    };

    // ldmatrix lane offsets (kk=0); kk=1 = ^32 (chunk j flips bit1 under XOR swizzle)
    u32 aoff[4], boff[2];
#pragma unroll
    for (int t = 0; t < 4; t++) {
        int ra = wm * 64 + t * 16 + (lane & 15);
        int j = lane >> 4;
        aoff[t] = (u32)(ra * 64 + ((j ^ ((ra >> 1) & 3)) << 4));
    }
#pragma unroll
    for (int u = 0; u < 2; u++) {
        int rb = wn * 32 + u * 16 + (lane & 7) + ((lane >> 4) & 1) * 8;
        int j = (lane >> 3) & 1;
        boff[u] = (u32)(rb * 64 + ((j ^ ((rb >> 1) & 3)) << 4));
    }

    issue(0);
    for (int c = 0; c < NCH; c++) {
        if (c + 1 < NCH) { issue(c + 1); cp_waitg<1>(); }
        else cp_waitg<0>();
        __syncthreads();
        u32 sA = sbase + (c & 1) * STAGE;
        u32 sB = sA + NA * 8192;
#pragma unroll
        for (int kk = 0; kk < 2; kk++) {
            u32 kx = kk << 5;
            u32 bfr[NB][2][4];
#pragma unroll
            for (int pb = 0; pb < NB; pb++)
#pragma unroll
                for (int u = 0; u < 2; u++)
                    ldm_x4(bfr[pb][u], sB + pb * 8192 + (boff[u] ^ kx));
#pragma unroll
            for (int pa = 0; pa < NA; pa++) {
                u32 af[4][4];
#pragma unroll
                for (int t = 0; t < 4; t++)
                    ldm_x4(af[t], sA + pa * 8192 + (aoff[t] ^ kx));
#pragma unroll
                for (int pb = 0; pb < NB; pb++) {
                    if (pa + pb < NB) {
#pragma unroll
                        for (int mi = 0; mi < 4; mi++)
#pragma unroll
                            for (int ni = 0; ni < 4; ni++)
                                mma16816(acc[mi][ni], af[mi], &bfr[pb][ni >> 1][(ni & 1) * 2]);
                    }
                }
            }
        }
        __syncthreads();
    }

    // ---- epilogue ----
    const int mrow = lane >> 2, nc2 = (lane & 3) * 2;
#pragma unroll
    for (int mi = 0; mi < 4; mi++) {
#pragma unroll
        for (int rp = 0; rp < 2; rp++) {
            long row = m0 + wm * 64 + mi * 16 + mrow + rp * 8;
            long rowoff = (long)z * sCz + row * ldc;
            float br = biasR ? biasR[row] : 0.f;
#pragma unroll
            for (int ni = 0; ni < 4; ni++) {
                int col = n0 + wn * 32 + ni * 8 + nc2;
                float v0 = acc[mi][ni][rp * 2 + 0] + br;
                float v1 = acc[mi][ni][rp * 2 + 1] + br;
                if (biasC) { v0 += biasC[col]; v1 += biasC[col + 1]; }
                if (Rh) {
                    float2 h = rd2bf(Rh, rowoff + col);
                    float2 m = rd2bf(Rm, rowoff + col);
                    float2 l = rd2bf(Rl, rowoff + col);
                    v0 += h.x + m.x + l.x;
                    v1 += h.y + m.y + l.y;
                }
                if (C) *(float2*)&C[rowoff + col] = make_float2(v0, v1);
                if (Ch) {
                    float h0 = __bfloat162float(__float2bfloat16(v0));
                    float h1 = __bfloat162float(__float2bfloat16(v1));
                    st2bf(Ch, rowoff + col, v0, v1);
                    float r0 = v0 - h0, r1 = v1 - h1;
                    st2bf(Cm, rowoff + col, r0, r1);
                    if (Cl) {
                        float m0f = __bfloat162float(__float2bfloat16(r0));
                        float m1f = __bfloat162float(__float2bfloat16(r1));
                        st2bf(Cl, rowoff + col, r0 - m0f, r1 - m1f);
                    }
                }
            }
        }
    }
}

// ------------- tiled transpose + 3-way bf16 split (X only) -------------
__global__ void tsplit(const float* __restrict__ src, bf16* __restrict__ h,
                       bf16* __restrict__ m, bf16* __restrict__ l, int R, int C)
{
    __shared__ float ts[32][33];
    int b = blockIdx.z;
    long o = (long)b * R * C;
    int c0 = blockIdx.x * 32, r0 = blockIdx.y * 32;
    int tx = threadIdx.x, ty = threadIdx.y;
#pragma unroll
    for (int i = 0; i < 4; i++)
        ts[ty + i * 8][tx] = src[o + (long)(r0 + ty + i * 8) * C + c0 + tx];
    __syncthreads();
#pragma unroll
    for (int i = 0; i < 4; i++) {
        int c = c0 + ty + i * 8;
        float v = ts[tx][ty + i * 8];
        long idx = o + (long)c * R + r0 + tx;
        bf16 hh = __float2bfloat16(v);
        float r1 = v - __bfloat162float(hh);
        bf16 mm = __float2bfloat16(r1);
        h[idx] = hh; m[idx] = mm;
        l[idx] = __float2bfloat16(r1 - __bfloat162float(mm));
    }
}

// ------------- all weight splits in one launch -------------
__global__ void split_all(const float* __restrict__ Wt, const float* __restrict__ Wp,
                          const float* __restrict__ Wg, const float* __restrict__ W2,
                          const float* __restrict__ W3)
{
    int i = blockIdx.x * 256 + threadIdx.x;
    if (i < C1 * CIN) {
        float v = Wt[i];
        bf16 h = __float2bfloat16(v); float r1 = v - __bfloat162float(h);
        bf16 m = __float2bfloat16(r1);
        g_Wth[i] = h; g_Wtm[i] = m; g_Wtl[i] = __float2bfloat16(r1 - __bfloat162float(m));
        v = Wp[i];
        h = __float2bfloat16(v); r1 = v - __bfloat162float(h);
        m = __float2bfloat16(r1);
        g_Wph[i] = h; g_Wpm[i] = m; g_Wpl[i] = __float2bfloat16(r1 - __bfloat162float(m));
        v = Wg[i];
        h = __float2bfloat16(v);
        g_Wgh[i] = h; g_Wgm[i] = __float2bfloat16(v - __bfloat162float(h));
        v = W2[i];
        h = __float2bfloat16(v);
        g_W2h[i] = h; g_W2m[i] = __float2bfloat16(v - __bfloat162float(h));
    }
    if (i < DD * CIN) {
        float v = W3[i];
        bf16 h = __float2bfloat16(v);
        g_W3h[i] = h; g_W3m[i] = __float2bfloat16(v - __bfloat162float(h));
    }
}

// ------------- softmax over f (reduce FS partials), emit bf16 h/m -------------
__global__ void softmax9(const float* __restrict__ Fp, bf16* __restrict__ Fh, bf16* __restrict__ Fm)
{
    int row = blockIdx.x, t = threadIdx.x;
    int b = row >> 8, c = row & 255;
    long base = (long)(b * FS) * 65536 + c * 256 + t;
    float v = 0.f;
#pragma unroll
    for (int s2 = 0; s2 < FS; s2++) v += Fp[base + (long)s2 * 65536];
    __shared__ float sh[256];
    sh[t] = v; __syncthreads();
    for (int o = 128; o; o >>= 1) { if (t < o) sh[t] = fmaxf(sh[t], sh[t + o]); __syncthreads(); }
    float mx = sh[0]; __syncthreads();
    float e = expf(v - mx);
    sh[t] = e; __syncthreads();
    for (int o = 128; o; o >>= 1) { if (t < o) sh[t] += sh[t + o]; __syncthreads(); }
    float r = e / sh[0];
    long o2 = (long)b * 65536 + c * 256 + t;
    bf16 h = __float2bfloat16(r);
    Fh[o2] = h;
    Fm[o2] = __float2bfloat16(r - __bfloat162float(h));
}

// ------------- zero accumulators -------------
__global__ void zero_kernel() {
    int i = blockIdx.x * blockDim.x + threadIdx.x;
    if (i < BB * KK * DD) g_Eacc[i] = 0.f;
    if (i < BB * KK)      g_Asum[i] = 0.f;
    if (i < BB * DD)      g_Es[i]   = 0.f;
}

// ------------- fused dist -> softmax(A) -> E accumulation -------------
__global__ __launch_bounds__(256) void encode_kernel(
    const float* __restrict__ ZDt,
    const float* __restrict__ codewords, const float* __restrict__ scale,
    float* __restrict__ Eacc, float* __restrict__ Asum)
{
    int b = blockIdx.y;
    __shared__ float cs[KK][DD + 1];
    __shared__ float cn[KK], sc[KK];
    __shared__ float xs[DD][33];
    __shared__ float Ash[8][KK];
    int tid = threadIdx.x, lane = tid & 31, wid = tid >> 5;

    for (int i = tid; i < KK * DD; i += 256) cs[i >> 7][i & 127] = codewords[i];
    if (tid < KK) sc[tid] = scale[tid];
    __syncthreads();
    if (tid < KK) {
        float s = 0.f;
        for (int d = 0; d < DD; d++) { float c = cs[tid][d]; s += c * c; }
        cn[tid] = s;
    }
    __syncthreads();

    float ereg[16];
#pragma unroll
    for (int i = 0; i < 16; i++) ereg[i] = 0.f;
    float asum_local = 0.f;
    int myk = tid >> 3, myd0 = tid & 7;

    for (int t = blockIdx.x; t < NN / 32; t += gridDim.x) {
        int n0 = t * 32;
#pragma unroll
        for (int r = 0; r < 4; r++) {
            int idx = r * 256 + tid;
            int n = idx >> 5, d4 = (idx & 31) * 4;
            float4 v = *(const float4*)(ZDt + ((long)b * NN + n0 + n) * DD + d4);
            xs[d4][n] = v.x; xs[d4 + 1][n] = v.y; xs[d4 + 2][n] = v.z; xs[d4 + 3][n] = v.w;
        }
        __syncthreads();
        for (int round = 0; round < 4; round++) {
            int n = round * 8 + wid;
            float xx = 0.f;
            for (int d = lane; d < DD; d += 32) { float x = xs[d][n]; xx += x * x; }
            for (int o = 16; o; o >>= 1) xx += __shfl_xor_sync(0xffffffffu, xx, o);
            float dot = 0.f;
#pragma unroll 8
            for (int d = 0; d < DD; d++) dot += xs[d][n] * cs[lane][d];
            float s = sc[lane] * (xx - 2.f * dot + cn[lane]);
            float mx = s;
            for (int o = 16; o; o >>= 1) mx = fmaxf(mx, __shfl_xor_sync(0xffffffffu, mx, o));
            float e = __expf(s - mx);
            float ssum = e;
            for (int o = 16; o; o >>= 1) ssum += __shfl_xor_sync(0xffffffffu, ssum, o);
            float a = e / ssum;
            Ash[wid][lane] = a;
            asum_local += a;
            __syncthreads();
#pragma unroll
            for (int nn2 = 0; nn2 < 8; nn2++) {
                float av = Ash[nn2][myk];
                int ncol = round * 8 + nn2;
#pragma unroll
                for (int i = 0; i < 16; i++)
                    ereg[i] += av * xs[myd0 + 8 * i][ncol];
            }
            __syncthreads();
        }
    }
#pragma unroll
    for (int i = 0; i < 16; i++)
        atomicAdd(&Eacc[((long)b * KK + myk) * DD + myd0 + 8 * i], ereg[i]);
    atomicAdd(&Asum[b * KK + lane], asum_local);
}

// ------------- BN over K + Es -------------
__global__ void bn_es_kernel(const float* __restrict__ Eacc, const float* __restrict__ Asum,
                             const float* __restrict__ codewords, float* __restrict__ Es)
{
    int k = blockIdx.x, tid = threadIdx.x;
    __shared__ double shs[256], shs2[256];
    float vals[4];
    double s = 0.0, s2 = 0.0;
#pragma unroll
    for (int i = 0; i < 4; i++) {
        int idx = tid + i * 256;
        int b = idx >> 7, d = idx & 127;
        float v = Eacc[((long)b * KK + k) * DD + d] - Asum[b * KK + k] * codewords[k * DD + d];
        vals[i] = v; s += v; s2 += (double)v * v;
    }
    shs[tid] = s; shs2[tid] = s2; __syncthreads();
    for (int o = 128; o; o >>= 1) {
        if (tid < o) { shs[tid] += shs[tid + o]; shs2[tid] += shs2[tid + o]; }
        __syncthreads();
    }
    double mean = shs[0] / 1024.0;
    double var = shs2[0] / 1024.0 - mean * mean;
    float inv = rsqrtf((float)var + 1e-5f);
    float mf = (float)mean;
#pragma unroll
    for (int i = 0; i < 4; i++) {
        int idx = tid + i * 256;
        int b = idx >> 7, d = idx & 127;
        float e = (vals[i] - mf) * inv;
        if (e > 0.f) atomicAdd(&Es[b * DD + d], e);
    }
}

// ------------- gamma = sigmoid(Es @ W_fc^T + b_fc) -------------
__global__ void gamma_kernel(const float* __restrict__ Es, const float* __restrict__ W_fc,
                             const float* __restrict__ b_fc, float* __restrict__ gam)
{
    int idx = blockIdx.x * blockDim.x + threadIdx.x;
    int b = idx / CIN, c = idx % CIN;
    float s = b_fc[c];
    for (int d = 0; d < DD; d++) s += Es[b * DD + d] * W_fc[c * DD + d];
    gam[idx] = 1.f / (1.f + expf(-s));
}

// ------------- transpose back + gamma scale -> output (B, C, N) -------------
__global__ void tscale_out(const float* __restrict__ Zt, const float* __restrict__ gam,
                           float* __restrict__ out)
{
    __shared__ float ts[32][33];
    int b = blockIdx.z;
    int n0 = blockIdx.x * 32, c0 = blockIdx.y * 32;
    int tx = threadIdx.x, ty = threadIdx.y;
#pragma unroll
    for (int i = 0; i < 4; i++)
        ts[ty + i * 8][tx] = Zt[((long)b * NN + n0 + ty + i * 8) * CIN + c0 + tx];
    __syncthreads();
#pragma unroll
    for (int i = 0; i < 4; i++) {
        int c = c0 + ty + i * 8;
        out[((long)b * CIN + c) * NN + n0 + tx] = ts[tx][ty + i * 8] * gam[b * CIN + c];
    }
}

// ------------- launch -------------
#define GA(T, p, s) T* p; cudaGetSymbolAddress((void**)&p, s)

extern "C" void kernel_launch(void* const* d_in, const int* in_sizes, int n_in,
                              void* d_out, int out_size)
{
    const float* X        = (const float*)d_in[0];
    const float* W_theta  = (const float*)d_in[1];
    const float* b_theta  = (const float*)d_in[2];
    const float* W_phi    = (const float*)d_in[3];
    const float* b_phi    = (const float*)d_in[4];
    const float* W_g      = (const float*)d_in[5];
    const float* b_g      = (const float*)d_in[6];
    const float* W2       = (const float*)d_in[7];
    const float* b2       = (const float*)d_in[8];
    const float* W3       = (const float*)d_in[9];
    const float* b3       = (const float*)d_in[10];
    const float* codewords= (const float*)d_in[11];
    const float* scale    = (const float*)d_in[12];
    const float* W_fc     = (const float*)d_in[13];
    const float* b_fc     = (const float*)d_in[14];

    GA(bf16, Xh, g_Xh); GA(bf16, Xm, g_Xm); GA(bf16, Xl, g_Xl);
    GA(bf16, Wth, g_Wth); GA(bf16, Wtm, g_Wtm); GA(bf16, Wtl, g_Wtl);
    GA(bf16, Wph, g_Wph); GA(bf16, Wpm, g_Wpm); GA(bf16, Wpl, g_Wpl);
    GA(bf16, Wgh, g_Wgh); GA(bf16, Wgm, g_Wgm);
    GA(bf16, W2h, g_W2h); GA(bf16, W2m, g_W2m);
    GA(bf16, W3h, g_W3h); GA(bf16, W3m, g_W3m);
    GA(bf16, Th, g_Th); GA(bf16, Tm, g_Tm); GA(bf16, Tl, g_Tl);
    GA(bf16, Ph, g_Phh); GA(bf16, Pm, g_Pmm); GA(bf16, Pl, g_Pll);
    GA(bf16, Gh, g_Gh); GA(bf16, Gm, g_Gm);
    GA(float, Fp, g_Fp);
    GA(bf16, Fh, g_Fh); GA(bf16, Fm, g_Fm);
    GA(bf16, Yh, g_Yh); GA(bf16, Ym, g_Ym);
    GA(float, Zt, g_Zt);
    GA(bf16, Zh, g_Zh); GA(bf16, Zm, g_Zm);
    GA(float, ZDt, g_ZDt);
    GA(float, Eacc, g_Eacc); GA(float, Asum, g_Asum);
    GA(float, Es, g_Es); GA(float, gamB, g_gam);

    const int SM6 = 2 * 6 * 8192;   // 98304
    const int SM3 = 2 * 4 * 8192;   // 65536
    cudaFuncSetAttribute(mma_gemm<6>, cudaFuncAttributeMaxDynamicSharedMemorySize, SM6);
    cudaFuncSetAttribute(mma_gemm<3>, cudaFuncAttributeMaxDynamicSharedMemorySize, SM3);

    // 1: zero, 2: tsplit X, 3: split_all, 4: phi, 5: g, 6: theta (ncu -s 5 -c 1 target)
    zero_kernel<<<128, 256>>>();
    tsplit<<<dim3(288, 16, BB), dim3(32, 8)>>>(X, Xh, Xm, Xl, CIN, NN);
    split_all<<<512, 256>>>(W_theta, W_phi, W_g, W2, W3);

    // phi: (C1 x 73728) = W_phi @ X^T, x6, output bf16 parts directly (row-bias)
    mma_gemm<6><<<dim3(576, 2, 1), 256, SM6>>>(
        Wph, Wpm, Wpl, CIN, 0, Xh, Xm, Xl, CIN, 0,
        nullptr, Ph, Pm, Pl, ROWS, 0, nullptr, b_phi, nullptr, nullptr, nullptr,
        16, 1);
    // g: (73728 x C1) = X^T @ W_g^T, x3 (col-bias)
    mma_gemm<3><<<dim3(2, 576, 1), 256, SM3>>>(
        Xh, Xm, nullptr, CIN, 0, Wgh, Wgm, nullptr, CIN, 0,
        nullptr, Gh, Gm, nullptr, C1, 0, b_g, nullptr, nullptr, nullptr, nullptr,
        16, 1);
    // theta: like phi
    mma_gemm<6><<<dim3(576, 2, 1), 256, SM6>>>(
        Wth, Wtm, Wtl, CIN, 0, Xh, Xm, Xl, CIN, 0,
        nullptr, Th, Tm, Tl, ROWS, 0, nullptr, b_theta, nullptr, nullptr, nullptr,
        16, 1);

    // f = theta @ phi^T (x6, split-K = FS chunks of 1024)
    mma_gemm<6><<<dim3(2, 2, BB * FS), 256, SM6>>>(
        Th, Tm, Tl, ROWS, NN, Ph, Pm, Pl, ROWS, NN,
        Fp, nullptr, nullptr, nullptr, C1, (long)C1 * C1,
        nullptr, nullptr, nullptr, nullptr, nullptr, 32, FS);
    softmax9<<<BB * C1, 256>>>(Fp, Fh, Fm);

    // y[n, c] = sum_d g[n, d] * f[c, d] per batch (x3)
    mma_gemm<3><<<dim3(2, 72, BB), 256, SM3>>>(
        Gh, Gm, nullptr, C1, (long)NN * C1, Fh, Fm, nullptr, C1, (long)C1 * C1,
        nullptr, Yh, Ym, nullptr, C1, (long)NN * C1,
        nullptr, nullptr, nullptr, nullptr, nullptr, 8, 1);

    // z = y @ W2^T + b2 + X (x3): fp32 + bf16 h/m
    mma_gemm<3><<<dim3(4, 576, 1), 256, SM3>>>(
        Yh, Ym, nullptr, C1, 0, W2h, W2m, nullptr, C1, 0,
        Zt, Zh, Zm, nullptr, CIN, 0, b2, nullptr, Xh, Xm, Xl, 8, 1);

    // z_ = z @ W3^T + b3 (x3)
    mma_gemm<3><<<dim3(1, 576, 1), 256, SM3>>>(
        Zh, Zm, nullptr, CIN, 0, W3h, W3m, nullptr, CIN, 0,
        ZDt, nullptr, nullptr, nullptr, DD, 0, b3, nullptr, nullptr, nullptr, nullptr,
        16, 1);

    encode_kernel<<<dim3(96, BB), 256>>>(ZDt, codewords, scale, Eacc, Asum);
    bn_es_kernel<<<KK, 256>>>(Eacc, Asum, codewords, Es);
    gamma_kernel<<<(BB * CIN) / 256, 256>>>(Es, W_fc, b_fc, gamB);
    tscale_out<<<dim3(288, 16, BB), dim3(32, 8)>>>(Zt, gamB, (float*)d_out);
}